// round 12
// baseline (speedup 1.0000x reference)
#include <cuda_runtime.h>
#include <cuda.h>
#include <cuda_bf16.h>
#include <math.h>
#include <stdint.h>

#define Bc   8192
#define DIMc 4096
#define Pc   64

// tcgen05 is only available on the arch-specific ('a') compile pass.
#if defined(__CUDA_ARCH__) && (defined(__CUDA_ARCH_FEAT_SM103_ALL) || defined(__CUDA_ARCH_FEAT_SM100_ALL))
#define TC_OK 1
#else
#define TC_OK 0
#endif

// ============================ PTX helpers ====================================
#if TC_OK
__device__ __forceinline__ uint32_t smem_u32(const void* p) {
    uint32_t a;
    asm("{ .reg .u64 t; cvta.to.shared.u64 t, %1; cvt.u32.u64 %0, t; }" : "=r"(a) : "l"(p));
    return a;
}
__device__ __forceinline__ uint32_t ctarank() {
    uint32_t r; asm("mov.u32 %0, %%cluster_ctarank;" : "=r"(r)); return r;
}
__device__ __forceinline__ void mbar_init(uint32_t a, uint32_t cnt) {
    asm volatile("mbarrier.init.shared.b64 [%0], %1;" :: "r"(a), "r"(cnt) : "memory");
}
__device__ __forceinline__ void mbar_wait(uint32_t a, uint32_t parity) {
    asm volatile(
        "{\n\t.reg .pred P;\n\t"
        "WL_%=:\n\t"
        "mbarrier.try_wait.parity.acquire.cta.shared::cta.b64 P, [%0], %1, 0x989680;\n\t"
        "@P bra WD_%=;\n\t"
        "bra WL_%=;\n\t"
        "WD_%=:\n\t}"
        :: "r"(a), "r"(parity) : "memory");
}
__device__ __forceinline__ void mbar_expect_tx(uint32_t a, uint32_t bytes) {
    asm volatile("mbarrier.arrive.expect_tx.shared.b64 _, [%0], %1;"
                 :: "r"(a), "r"(bytes) : "memory");
}
__device__ __forceinline__ void tma2d(uint32_t dst, const CUtensorMap* m,
                                      int x, int y, uint32_t mbar) {
    asm volatile(
        "cp.async.bulk.tensor.2d.shared::cta.global.tile.mbarrier::complete_tx::bytes "
        "[%0], [%1, {%2, %3}], [%4];"
        :: "r"(dst), "l"(m), "r"(x), "r"(y), "r"(mbar) : "memory");
}
__device__ __forceinline__ void tma2d_mc(uint32_t dst, const CUtensorMap* m,
                                         int x, int y, uint32_t mbar, uint16_t mask) {
    asm volatile(
        "cp.async.bulk.tensor.2d.shared::cluster.global.tile.mbarrier::complete_tx::bytes.multicast::cluster "
        "[%0], [%1, {%2, %3}], [%4], %5;"
        :: "r"(dst), "l"(m), "r"(x), "r"(y), "r"(mbar), "h"(mask) : "memory");
}
__device__ __forceinline__ void tmem_alloc(uint32_t dst_smem, uint32_t ncols) {
    asm volatile("tcgen05.alloc.cta_group::1.sync.aligned.shared::cta.b32 [%0], %1;"
                 :: "r"(dst_smem), "r"(ncols) : "memory");
}
__device__ __forceinline__ void tmem_dealloc(uint32_t tmem, uint32_t ncols) {
    asm volatile("tcgen05.dealloc.cta_group::1.sync.aligned.b32 %0, %1;" :: "r"(tmem), "r"(ncols));
}
__device__ __forceinline__ void tmem_relinquish() {
    asm volatile("tcgen05.relinquish_alloc_permit.cta_group::1.sync.aligned;");
}
__device__ __forceinline__ void tc_commit_mc(uint32_t mbar, uint16_t mask) {
    asm volatile(
        "tcgen05.commit.cta_group::1.mbarrier::arrive::one.shared::cluster.multicast::cluster.b64 [%0], %1;"
        :: "r"(mbar), "h"(mask) : "memory");
}
__device__ __forceinline__ void tc_fence_after() {
    asm volatile("tcgen05.fence::after_thread_sync;" ::: "memory");
}
__device__ __forceinline__ void async_fence() {
    asm volatile("fence.proxy.async.shared::cta;" ::: "memory");
}
__device__ __forceinline__ void cluster_sync_all() {
    asm volatile("barrier.cluster.arrive.aligned;" ::: "memory");
    asm volatile("barrier.cluster.wait.aligned;" ::: "memory");
}
__device__ __forceinline__ void mma_f16_ss(uint32_t d, uint64_t ad, uint64_t bd,
                                           uint32_t idesc, uint32_t enable) {
    asm volatile(
        "{\n\t.reg .pred p;\n\t"
        "setp.ne.u32 p, %4, 0;\n\t"
        "tcgen05.mma.cta_group::1.kind::f16 [%0], %1, %2, %3, {%5, %5, %5, %5}, p;\n\t}"
        :: "r"(d), "l"(ad), "l"(bd), "r"(idesc), "r"(enable), "r"(0u) : "memory");
}
#define TC_LD_X32(r, addr) \
    asm volatile( \
        "tcgen05.ld.sync.aligned.32x32b.x32.b32 " \
        "{%0, %1, %2, %3, %4, %5, %6, %7, " \
        " %8, %9, %10, %11, %12, %13, %14, %15, " \
        " %16, %17, %18, %19, %20, %21, %22, %23, " \
        " %24, %25, %26, %27, %28, %29, %30, %31}, [%32];" \
        : "=r"((r)[0]),  "=r"((r)[1]),  "=r"((r)[2]),  "=r"((r)[3]), \
          "=r"((r)[4]),  "=r"((r)[5]),  "=r"((r)[6]),  "=r"((r)[7]), \
          "=r"((r)[8]),  "=r"((r)[9]),  "=r"((r)[10]), "=r"((r)[11]), \
          "=r"((r)[12]), "=r"((r)[13]), "=r"((r)[14]), "=r"((r)[15]), \
          "=r"((r)[16]), "=r"((r)[17]), "=r"((r)[18]), "=r"((r)[19]), \
          "=r"((r)[20]), "=r"((r)[21]), "=r"((r)[22]), "=r"((r)[23]), \
          "=r"((r)[24]), "=r"((r)[25]), "=r"((r)[26]), "=r"((r)[27]), \
          "=r"((r)[28]), "=r"((r)[29]), "=r"((r)[30]), "=r"((r)[31]) \
        : "r"(addr))
#define TC_WAIT_LD() asm volatile("tcgen05.wait::ld.sync.aligned;" ::: "memory")

// SW128 descriptor: layout=2, version=1, SBO=64, LBO=1
__device__ __forceinline__ uint64_t make_desc(uint32_t addr) {
    const uint64_t base = (uint64_t(2) << 61) | (uint64_t(1) << 46)
                        | (uint64_t(64) << 32) | (uint64_t(1) << 16);
    return base | ((uint64_t)(addr >> 4) & 0x3FFF);
}
#endif // TC_OK

// ============================ scratch globals ================================
// Packed operand layout: [row][2*DIMc] bf16, each 32-K chunk = 128B row:
//   [hi(k0..31) 64B | lo(k0..31) 64B]
__device__ float g_scale[Bc];
__device__ float g_buf1[(size_t)Bc * DIMc];                 // pre-LN output (fp32)
__device__ float g_phase[(size_t)Bc * 128];                 // [kz | qz] pre-activation
__device__ float g_bkq[128];
__device__ __nv_bfloat16 g_xp [(size_t)Bc   * 2 * DIMc];
__device__ __nv_bfloat16 g_wvp[(size_t)DIMc * 2 * DIMc];
__device__ __nv_bfloat16 g_wop[(size_t)DIMc * 2 * DIMc];
__device__ __nv_bfloat16 g_np [(size_t)Bc   * 2 * DIMc];
__device__ __nv_bfloat16 g_wkqp[(size_t)128 * 2 * DIMc];

// ============================ split fp32 -> packed hi|lo =====================
__device__ __forceinline__ void split1(float v, unsigned short &h, unsigned short &l) {
    __nv_bfloat16 hb = __float2bfloat16(v);
    float r = v - __bfloat162float(hb);
    h = __bfloat16_as_ushort(hb);
    l = __bfloat16_as_ushort(__float2bfloat16(r));
}

// one thread per 32-element chunk (chunks are row-major-contiguous)
__global__ void __launch_bounds__(256)
split_pack(const float* __restrict__ in, __nv_bfloat16* __restrict__ outp,
           unsigned nchunks)
{
    unsigned idx = blockIdx.x * 256 + threadIdx.x;
    if (idx >= nchunks) return;
    const float4* src = (const float4*)(in + (size_t)idx * 32);
    unsigned short h[32], l[32];
#pragma unroll
    for (int q = 0; q < 8; q++) {
        float4 v = src[q];
        split1(v.x, h[4*q+0], l[4*q+0]);
        split1(v.y, h[4*q+1], l[4*q+1]);
        split1(v.z, h[4*q+2], l[4*q+2]);
        split1(v.w, h[4*q+3], l[4*q+3]);
    }
    uint4* dst = (uint4*)(outp + (size_t)idx * 64);
#pragma unroll
    for (int q = 0; q < 4; q++) dst[q]     = ((const uint4*)h)[q];
#pragma unroll
    for (int q = 0; q < 4; q++) dst[4 + q] = ((const uint4*)l)[q];
}

__global__ void prep_bias(const float* __restrict__ bk, const float* __restrict__ bq,
                          float* __restrict__ bkq)
{
    int t = threadIdx.x;
    bkq[t] = (t < 64) ? bk[t] : bq[t - 64];
}

// ============================ tcgen05 TMA GEMM ===============================
// BM=256 (two M=128 accumulators), KC=32 packed hi|lo, 3-stage TMA pipeline.
// Deferred-empty-wait mainloop (tensor queue never drains) + cluster(1,2,1)
// B-tile multicast cooperative slicing (halves B LTS traffic).
// MODE 0: out = (acc + bias[n]) * aux[m]
// MODE 1: out = aux[m][n] + bias[n] + acc
// MODE 2: out = acc + bias[n]
#define BMg 256
#define KCg 32
#define NCHUNK (DIMc / KCg)      // 128
#define NSTAGE 3
#define SM_DATA0 1024

template<int MODE, int BNv, int OUTW>
__global__ void __launch_bounds__(256, 1) __cluster_dims__(1, 2, 1)
tc_gemm(const __grid_constant__ CUtensorMap tmA,
        const __grid_constant__ CUtensorMap tmB,
        const float* __restrict__ bias, const float* __restrict__ aux,
        float* __restrict__ out)
{
#if TC_OK
    constexpr int ST_B = BMg * 128;                     // A: 32 KB, then B
    constexpr int STAGE_SZ = (BMg + BNv) * 128;
    constexpr uint32_t TXB = (uint32_t)STAGE_SZ;
    constexpr int HALF_ROWS = BNv / 2;
    constexpr int HALF_BYTES = HALF_ROWS * 128;
    constexpr uint32_t IDESC = 0x08000490u | ((uint32_t)(BNv / 8) << 17);  // M=128

    extern __shared__ __align__(1024) char smem[];
    const uint32_t sb = smem_u32(smem);
    const int tid = threadIdx.x;
    const int wid = tid >> 5;
    const int lid = tid & 31;
    const int m0 = blockIdx.y * BMg;
    const int n0 = blockIdx.x * BNv;
    const uint32_t rank = ctarank();

    // smem: [0] tmem ptr; full[s] @ 16+8s; empty[s] @ 48+8s; stages @ 1024
    if (wid == 0) tmem_alloc(sb + 0, 512);
    if (tid == 0) {
#pragma unroll
        for (int s = 0; s < NSTAGE; s++) {
            mbar_init(sb + 16 + 8 * s, 1);   // full: local expect_tx arrive
            mbar_init(sb + 48 + 8 * s, 2);   // empty: commits from BOTH CTAs
        }
        async_fence();
    }
    __syncthreads();
    cluster_sync_all();          // peer barriers visible before any multicast
    uint32_t tmem;
    asm volatile("ld.shared.b32 %0, [%1];" : "=r"(tmem) : "r"(sb + 0));

    if (tid == 0) {
        int fph[NSTAGE] = {0, 0, 0};
        int eph[NSTAGE] = {0, 0, 0};
        // prologue: stages 0..2 hold chunks 0..2
#pragma unroll
        for (int s = 0; s < NSTAGE; s++) {
            uint32_t st = sb + SM_DATA0 + s * STAGE_SZ;
            mbar_expect_tx(sb + 16 + 8 * s, TXB);
            tma2d(st, &tmA, s * 64, m0, sb + 16 + 8 * s);
            tma2d_mc(st + ST_B + rank * HALF_BYTES, &tmB,
                     s * 64, n0 + (int)rank * HALF_ROWS, sb + 16 + 8 * s, 3);
        }
        for (int i = 0; i < NCHUNK; i++) {
            const int s = i % NSTAGE;
            mbar_wait(sb + 16 + 8 * s, fph[s]); fph[s] ^= 1;
            uint32_t sa = sb + SM_DATA0 + s * STAGE_SZ;
            uint64_t bD = make_desc(sa + ST_B);
#pragma unroll
            for (int d = 0; d < 2; d++) {
                uint64_t aD = make_desc(sa + d * 16384);
                uint32_t D = tmem + d * BNv;
                mma_f16_ss(D, aD + 0, bD + 0, IDESC, (i > 0) ? 1u : 0u);  // hi*hi
                mma_f16_ss(D, aD + 2, bD + 2, IDESC, 1u);
                mma_f16_ss(D, aD + 0, bD + 4, IDESC, 1u);                 // hi*lo
                mma_f16_ss(D, aD + 2, bD + 6, IDESC, 1u);
                mma_f16_ss(D, aD + 4, bD + 0, IDESC, 1u);                 // lo*hi
                mma_f16_ss(D, aD + 6, bD + 2, IDESC, 1u);
            }
            tc_commit_mc(sb + 48 + 8 * s, 3);
            // Deferred refill: stage (i-1)%3 held chunk i-1; once BOTH CTAs'
            // MMAs on it retire (while chunk i executes), load chunk i+2.
            if (i >= 1 && i + 2 < NCHUNK) {
                const int sp = (i - 1) % NSTAGE;          // == (i+2) % NSTAGE
                mbar_wait(sb + 48 + 8 * sp, eph[sp]); eph[sp] ^= 1;
                uint32_t sq = sb + SM_DATA0 + sp * STAGE_SZ;
                mbar_expect_tx(sb + 16 + 8 * sp, TXB);
                tma2d(sq, &tmA, (i + 2) * 64, m0, sb + 16 + 8 * sp);
                tma2d_mc(sq + ST_B + rank * HALF_BYTES, &tmB,
                         (i + 2) * 64, n0 + (int)rank * HALF_ROWS,
                         sb + 16 + 8 * sp, 3);
            }
        }
        // wait for last chunk's commits (in-order pipe => all MMAs done)
        const int ls = (NCHUNK - 1) % NSTAGE;
        mbar_wait(sb + 48 + 8 * ls, eph[ls]);
    }
    __syncthreads();
    tc_fence_after();

    // ---- epilogue: 8 warps. wid<4 -> D0 (rows m0+0..127), wid>=4 -> D1.
    {
        const int dsel = wid >> 2;
        const int row = m0 + dsel * 128 + (wid & 3) * 32 + lid;
        const uint32_t dbase = tmem + dsel * BNv;
        float sc = 0.f;
        if (MODE == 0) sc = __ldg(&aux[row]);
#pragma unroll
        for (int cb = 0; cb < BNv / 32; cb++) {
            uint32_t r[32];
            TC_LD_X32(r, dbase + cb * 32);
            TC_WAIT_LD();
            const int nc = n0 + cb * 32;
            float o[32];
#pragma unroll
            for (int j = 0; j < 32; j++) o[j] = __uint_as_float(r[j]);

            const float4* bp = (const float4*)(bias + nc);
            if (MODE == 0) {
#pragma unroll
                for (int q = 0; q < 8; q++) {
                    float4 bv4 = bp[q];
                    o[4*q+0] = (o[4*q+0] + bv4.x) * sc;
                    o[4*q+1] = (o[4*q+1] + bv4.y) * sc;
                    o[4*q+2] = (o[4*q+2] + bv4.z) * sc;
                    o[4*q+3] = (o[4*q+3] + bv4.w) * sc;
                }
            } else if (MODE == 1) {
                const float4* xp = (const float4*)(aux + (size_t)row * OUTW + nc);
#pragma unroll
                for (int q = 0; q < 8; q++) {
                    float4 bv4 = bp[q];
                    float4 xv4 = xp[q];
                    o[4*q+0] += bv4.x + xv4.x;
                    o[4*q+1] += bv4.y + xv4.y;
                    o[4*q+2] += bv4.z + xv4.z;
                    o[4*q+3] += bv4.w + xv4.w;
                }
            } else {
#pragma unroll
                for (int q = 0; q < 8; q++) {
                    float4 bv4 = bp[q];
                    o[4*q+0] += bv4.x;
                    o[4*q+1] += bv4.y;
                    o[4*q+2] += bv4.z;
                    o[4*q+3] += bv4.w;
                }
            }
            float4* op = (float4*)(out + (size_t)row * OUTW + nc);
#pragma unroll
            for (int q = 0; q < 8; q++)
                op[q] = make_float4(o[4*q+0], o[4*q+1], o[4*q+2], o[4*q+3]);
        }
    }
    __syncthreads();
    if (wid == 0) {
        tmem_relinquish();
        tmem_dealloc(tmem, 512);
    }
    cluster_sync_all();          // no CTA exits with peer multicast in flight
#else
    asm volatile("trap;");
#endif
}

// ============================ phase post-process =============================
__global__ void __launch_bounds__(256)
phase_post(const float* __restrict__ z, float* __restrict__ scale_out)
{
    const int t = threadIdx.x;
    const int warp = t >> 5, lane = t & 31;
    const int row = blockIdx.x * 8 + warp;
    const float* zr = z + (size_t)row * 128;
    const float PIf = 3.14159265358979323846f;

    float zk0 = zr[lane],      zq0 = zr[64 + lane];
    float zk1 = zr[32 + lane], zq1 = zr[96 + lane];
    float c = cosf((tanhf(zk0) - tanhf(zq0)) * PIf)
            + cosf((tanhf(zk1) - tanhf(zq1)) * PIf);
#pragma unroll
    for (int off = 16; off > 0; off >>= 1)
        c += __shfl_xor_sync(0xFFFFFFFFu, c, off);
    if (lane == 0) {
        float align = c;
        float gain  = log1pf(expf(align / 64.f + 0.5f));
        scale_out[row] = align * gain / 64.f;
    }
}

// ============================ K3: LayerNorm -> packed hi|lo ==================
__global__ void __launch_bounds__(256)
ln_kernel(const float* __restrict__ in, const float* __restrict__ g,
          const float* __restrict__ b, __nv_bfloat16* __restrict__ np)
{
    const int row = blockIdx.x;
    const float* rp = in + (size_t)row * DIMc;
    const int t = threadIdx.x;

    float4 v[4];
    float s = 0.f, s2 = 0.f;
#pragma unroll
    for (int i = 0; i < 4; i++) {
        v[i] = *(const float4*)(rp + 4 * (t + 256 * i));
        s  += v[i].x + v[i].y + v[i].z + v[i].w;
        s2 += v[i].x * v[i].x + v[i].y * v[i].y + v[i].z * v[i].z + v[i].w * v[i].w;
    }
#pragma unroll
    for (int off = 16; off > 0; off >>= 1) {
        s  += __shfl_xor_sync(0xFFFFFFFFu, s, off);
        s2 += __shfl_xor_sync(0xFFFFFFFFu, s2, off);
    }
    __shared__ float rs[8], rs2[8];
    __shared__ float mu_s, rstd_s;
    const int wid = t >> 5, lane = t & 31;
    if (lane == 0) { rs[wid] = s; rs2[wid] = s2; }
    __syncthreads();
    if (t == 0) {
        float ts = 0.f, ts2 = 0.f;
#pragma unroll
        for (int i = 0; i < 8; i++) { ts += rs[i]; ts2 += rs2[i]; }
        float mu  = ts / (float)DIMc;
        float var = ts2 / (float)DIMc - mu * mu;
        mu_s   = mu;
        rstd_s = rsqrtf(fmaxf(var, 0.f) + 1e-5f);
    }
    __syncthreads();
    const float mu = mu_s, rstd = rstd_s;
    __nv_bfloat16* nrow = np + (size_t)row * (2 * DIMc);
#pragma unroll
    for (int i = 0; i < 4; i++) {
        int c = 4 * (t + 256 * i);
        float4 gg = *(const float4*)(g + c);
        float4 bb = *(const float4*)(b + c);
        float4 ov;
        ov.x = (v[i].x - mu) * rstd * gg.x + bb.x;
        ov.y = (v[i].y - mu) * rstd * gg.y + bb.y;
        ov.z = (v[i].z - mu) * rstd * gg.z + bb.z;
        ov.w = (v[i].w - mu) * rstd * gg.w + bb.w;
        ushort4 h, l;
        split1(ov.x, h.x, l.x); split1(ov.y, h.y, l.y);
        split1(ov.z, h.z, l.z); split1(ov.w, h.w, l.w);
        const int chunk = c >> 5, off = c & 31;
        __nv_bfloat16* base = nrow + chunk * 64 + off;
        *(ushort4*)(base)      = h;
        *(ushort4*)(base + 32) = l;
    }
}

// ============================ launch =========================================
typedef CUresult (*PFN_encodeTiled)(CUtensorMap*, CUtensorMapDataType, cuuint32_t,
                                    void*, const cuuint64_t*, const cuuint64_t*,
                                    const cuuint32_t*, const cuuint32_t*,
                                    CUtensorMapInterleave, CUtensorMapSwizzle,
                                    CUtensorMapL2promotion, CUtensorMapFloatOOBfill);

static void enc_map(PFN_encodeTiled f, CUtensorMap* m, void* ptr,
                    unsigned long long rows, unsigned box_rows)
{
    cuuint64_t dims[2]    = { (cuuint64_t)(2 * DIMc), (cuuint64_t)rows };
    cuuint64_t strides[1] = { (cuuint64_t)(2 * DIMc) * 2 };   // bytes per row
    cuuint32_t box[2]     = { 64u, box_rows };
    cuuint32_t es[2]      = { 1u, 1u };
    f(m, CU_TENSOR_MAP_DATA_TYPE_BFLOAT16, 2, ptr, dims, strides, box, es,
      CU_TENSOR_MAP_INTERLEAVE_NONE, CU_TENSOR_MAP_SWIZZLE_128B,
      CU_TENSOR_MAP_L2_PROMOTION_L2_128B, CU_TENSOR_MAP_FLOAT_OOB_FILL_NONE);
}

extern "C" void kernel_launch(void* const* d_in, const int* in_sizes, int n_in,
                              void* d_out, int out_size)
{
    (void)in_sizes; (void)n_in; (void)out_size;
    const float* x   = (const float*)d_in[0];
    const float* Wk  = (const float*)d_in[1];
    const float* bk  = (const float*)d_in[2];
    const float* Wq  = (const float*)d_in[3];
    const float* bq  = (const float*)d_in[4];
    const float* Wv  = (const float*)d_in[5];
    const float* bv  = (const float*)d_in[6];
    const float* lng = (const float*)d_in[7];
    const float* lnb = (const float*)d_in[8];
    const float* Wo  = (const float*)d_in[9];
    const float* bo  = (const float*)d_in[10];
    float* out = (float*)d_out;

    void *p;
    cudaGetSymbolAddress(&p, g_scale); float* psc = (float*)p;
    cudaGetSymbolAddress(&p, g_buf1);  float* pb1 = (float*)p;
    cudaGetSymbolAddress(&p, g_phase); float* pph = (float*)p;
    cudaGetSymbolAddress(&p, g_bkq);   float* pbkq = (float*)p;
    cudaGetSymbolAddress(&p, g_xp);    __nv_bfloat16* xp  = (__nv_bfloat16*)p;
    cudaGetSymbolAddress(&p, g_wvp);   __nv_bfloat16* wvp = (__nv_bfloat16*)p;
    cudaGetSymbolAddress(&p, g_wop);   __nv_bfloat16* wop = (__nv_bfloat16*)p;
    cudaGetSymbolAddress(&p, g_np);    __nv_bfloat16* np  = (__nv_bfloat16*)p;
    cudaGetSymbolAddress(&p, g_wkqp);  __nv_bfloat16* wkqp = (__nv_bfloat16*)p;

    // tensor maps (driver entry point; no -lcuda link needed)
    PFN_encodeTiled encf = nullptr;
    {
        void* fp = nullptr;
        cudaDriverEntryPointQueryResult qr;
        cudaGetDriverEntryPoint("cuTensorMapEncodeTiled", &fp, cudaEnableDefault, &qr);
        encf = (PFN_encodeTiled)fp;
    }
    CUtensorMap tmX, tmWv, tmWo, tmN, tmWkq;
    enc_map(encf, &tmX,   xp,   Bc,   256);   // A role: full 256-row box
    enc_map(encf, &tmWv,  wvp,  DIMc, 128);   // B role: half-tile box (multicast slice)
    enc_map(encf, &tmWo,  wop,  DIMc, 128);
    enc_map(encf, &tmN,   np,   Bc,   256);
    enc_map(encf, &tmWkq, wkqp, 128,  64);    // B role for BNv=128: half = 64 rows

    constexpr int SMEM_256 = SM_DATA0 + NSTAGE * ((BMg + 256) * 128);  // 197,632
    constexpr int SMEM_128 = SM_DATA0 + NSTAGE * ((BMg + 128) * 128);  // 148,480
    cudaFuncSetAttribute((tc_gemm<0,256,DIMc>), cudaFuncAttributeMaxDynamicSharedMemorySize, SMEM_256);
    cudaFuncSetAttribute((tc_gemm<1,256,DIMc>), cudaFuncAttributeMaxDynamicSharedMemorySize, SMEM_256);
    cudaFuncSetAttribute((tc_gemm<2,128,128>),  cudaFuncAttributeMaxDynamicSharedMemorySize, SMEM_128);

    const unsigned nX = Bc * (DIMc / 32);          // 32-elem chunks
    const unsigned nW = DIMc * (DIMc / 32);
    const unsigned nP = 64 * (DIMc / 32);

    split_pack<<<(nX + 255) / 256, 256>>>(x,  xp,  nX);
    split_pack<<<(nW + 255) / 256, 256>>>(Wv, wvp, nW);
    split_pack<<<(nW + 255) / 256, 256>>>(Wo, wop, nW);
    split_pack<<<(nP + 255) / 256, 256>>>(Wk, wkqp, nP);
    split_pack<<<(nP + 255) / 256, 256>>>(Wq, wkqp + (size_t)64 * 2 * DIMc, nP);
    prep_bias<<<1, 128>>>(bk, bq, pbkq);

    // phase GEMM: z = x @ [Wk;Wq]^T + bkq   (8192 x 128)
    tc_gemm<2,128,128><<<dim3(1, Bc / BMg), 256, SMEM_128>>>(tmX, tmWkq, pbkq, nullptr, pph);
    phase_post<<<Bc / 8, 256>>>(pph, psc);

    tc_gemm<0,256,DIMc><<<dim3(DIMc / 256, Bc / BMg), 256, SMEM_256>>>(tmX, tmWv, bv, psc, pb1);
    ln_kernel<<<Bc, 256>>>(pb1, lng, lnb, np);
    tc_gemm<1,256,DIMc><<<dim3(DIMc / 256, Bc / BMg), 256, SMEM_256>>>(tmN, tmWo, bo, x, out);
}

// round 13
// speedup vs baseline: 1.0431x; 1.0431x over previous
#include <cuda_runtime.h>
#include <cuda.h>
#include <cuda_bf16.h>
#include <math.h>
#include <stdint.h>

#define Bc   8192
#define DIMc 4096
#define Pc   64

// tcgen05 is only available on the arch-specific ('a') compile pass.
#if defined(__CUDA_ARCH__) && (defined(__CUDA_ARCH_FEAT_SM103_ALL) || defined(__CUDA_ARCH_FEAT_SM100_ALL))
#define TC_OK 1
#else
#define TC_OK 0
#endif

// ============================ PTX helpers ====================================
#if TC_OK
__device__ __forceinline__ uint32_t smem_u32(const void* p) {
    uint32_t a;
    asm("{ .reg .u64 t; cvta.to.shared.u64 t, %1; cvt.u32.u64 %0, t; }" : "=r"(a) : "l"(p));
    return a;
}
__device__ __forceinline__ void mbar_init(uint32_t a, uint32_t cnt) {
    asm volatile("mbarrier.init.shared.b64 [%0], %1;" :: "r"(a), "r"(cnt) : "memory");
}
__device__ __forceinline__ void mbar_wait(uint32_t a, uint32_t parity) {
    asm volatile(
        "{\n\t.reg .pred P;\n\t"
        "WL_%=:\n\t"
        "mbarrier.try_wait.parity.acquire.cta.shared::cta.b64 P, [%0], %1, 0x989680;\n\t"
        "@P bra WD_%=;\n\t"
        "bra WL_%=;\n\t"
        "WD_%=:\n\t}"
        :: "r"(a), "r"(parity) : "memory");
}
__device__ __forceinline__ void mbar_expect_tx(uint32_t a, uint32_t bytes) {
    asm volatile("mbarrier.arrive.expect_tx.shared.b64 _, [%0], %1;"
                 :: "r"(a), "r"(bytes) : "memory");
}
__device__ __forceinline__ void tma2d(uint32_t dst, const CUtensorMap* m,
                                      int x, int y, uint32_t mbar) {
    asm volatile(
        "cp.async.bulk.tensor.2d.shared::cta.global.tile.mbarrier::complete_tx::bytes "
        "[%0], [%1, {%2, %3}], [%4];"
        :: "r"(dst), "l"(m), "r"(x), "r"(y), "r"(mbar) : "memory");
}
__device__ __forceinline__ void tmem_alloc(uint32_t dst_smem, uint32_t ncols) {
    asm volatile("tcgen05.alloc.cta_group::1.sync.aligned.shared::cta.b32 [%0], %1;"
                 :: "r"(dst_smem), "r"(ncols) : "memory");
}
__device__ __forceinline__ void tmem_dealloc(uint32_t tmem, uint32_t ncols) {
    asm volatile("tcgen05.dealloc.cta_group::1.sync.aligned.b32 %0, %1;" :: "r"(tmem), "r"(ncols));
}
__device__ __forceinline__ void tmem_relinquish() {
    asm volatile("tcgen05.relinquish_alloc_permit.cta_group::1.sync.aligned;");
}
__device__ __forceinline__ void tc_commit(uint32_t mbar) {
    asm volatile("tcgen05.commit.cta_group::1.mbarrier::arrive::one.shared::cluster.b64 [%0];"
                 :: "r"(mbar) : "memory");
}
__device__ __forceinline__ void tc_fence_after() {
    asm volatile("tcgen05.fence::after_thread_sync;" ::: "memory");
}
__device__ __forceinline__ void async_fence() {
    asm volatile("fence.proxy.async.shared::cta;" ::: "memory");
}
__device__ __forceinline__ void mma_f16_ss(uint32_t d, uint64_t ad, uint64_t bd,
                                           uint32_t idesc, uint32_t enable) {
    asm volatile(
        "{\n\t.reg .pred p;\n\t"
        "setp.ne.u32 p, %4, 0;\n\t"
        "tcgen05.mma.cta_group::1.kind::f16 [%0], %1, %2, %3, {%5, %5, %5, %5}, p;\n\t}"
        :: "r"(d), "l"(ad), "l"(bd), "r"(idesc), "r"(enable), "r"(0u) : "memory");
}
#define TC_LD_X32(r, addr) \
    asm volatile( \
        "tcgen05.ld.sync.aligned.32x32b.x32.b32 " \
        "{%0, %1, %2, %3, %4, %5, %6, %7, " \
        " %8, %9, %10, %11, %12, %13, %14, %15, " \
        " %16, %17, %18, %19, %20, %21, %22, %23, " \
        " %24, %25, %26, %27, %28, %29, %30, %31}, [%32];" \
        : "=r"((r)[0]),  "=r"((r)[1]),  "=r"((r)[2]),  "=r"((r)[3]), \
          "=r"((r)[4]),  "=r"((r)[5]),  "=r"((r)[6]),  "=r"((r)[7]), \
          "=r"((r)[8]),  "=r"((r)[9]),  "=r"((r)[10]), "=r"((r)[11]), \
          "=r"((r)[12]), "=r"((r)[13]), "=r"((r)[14]), "=r"((r)[15]), \
          "=r"((r)[16]), "=r"((r)[17]), "=r"((r)[18]), "=r"((r)[19]), \
          "=r"((r)[20]), "=r"((r)[21]), "=r"((r)[22]), "=r"((r)[23]), \
          "=r"((r)[24]), "=r"((r)[25]), "=r"((r)[26]), "=r"((r)[27]), \
          "=r"((r)[28]), "=r"((r)[29]), "=r"((r)[30]), "=r"((r)[31]) \
        : "r"(addr))
#define TC_WAIT_LD() asm volatile("tcgen05.wait::ld.sync.aligned;" ::: "memory")

// SW128 descriptor: layout=2, version=1, SBO=64, LBO=1
__device__ __forceinline__ uint64_t make_desc(uint32_t addr) {
    const uint64_t base = (uint64_t(2) << 61) | (uint64_t(1) << 46)
                        | (uint64_t(64) << 32) | (uint64_t(1) << 16);
    return base | ((uint64_t)(addr >> 4) & 0x3FFF);
}
#endif // TC_OK

// ============================ scratch globals ================================
// Packed operand layout: [row][2*DIMc] bf16, each 32-K chunk = 128B row:
//   [hi(k0..31) 64B | lo(k0..31) 64B]
__device__ float g_scale[Bc];
__device__ float g_buf1[(size_t)Bc * DIMc];                 // pre-LN output (fp32)
__device__ float g_phase[(size_t)Bc * 128];                 // [kz | qz] pre-activation
__device__ float g_bkq[128];
__device__ __nv_bfloat16 g_xp [(size_t)Bc   * 2 * DIMc];
__device__ __nv_bfloat16 g_wvp[(size_t)DIMc * 2 * DIMc];
__device__ __nv_bfloat16 g_wop[(size_t)DIMc * 2 * DIMc];
__device__ __nv_bfloat16 g_np [(size_t)Bc   * 2 * DIMc];
__device__ __nv_bfloat16 g_wkqp[(size_t)128 * 2 * DIMc];

// ============================ split fp32 -> packed hi|lo =====================
__device__ __forceinline__ void split1(float v, unsigned short &h, unsigned short &l) {
    __nv_bfloat16 hb = __float2bfloat16(v);
    float r = v - __bfloat162float(hb);
    h = __bfloat16_as_ushort(hb);
    l = __bfloat16_as_ushort(__float2bfloat16(r));
}

// one thread per 32-element chunk (chunks are row-major-contiguous)
__global__ void __launch_bounds__(256)
split_pack(const float* __restrict__ in, __nv_bfloat16* __restrict__ outp,
           unsigned nchunks)
{
    unsigned idx = blockIdx.x * 256 + threadIdx.x;
    if (idx >= nchunks) return;
    const float4* src = (const float4*)(in + (size_t)idx * 32);
    unsigned short h[32], l[32];
#pragma unroll
    for (int q = 0; q < 8; q++) {
        float4 v = src[q];
        split1(v.x, h[4*q+0], l[4*q+0]);
        split1(v.y, h[4*q+1], l[4*q+1]);
        split1(v.z, h[4*q+2], l[4*q+2]);
        split1(v.w, h[4*q+3], l[4*q+3]);
    }
    uint4* dst = (uint4*)(outp + (size_t)idx * 64);
#pragma unroll
    for (int q = 0; q < 4; q++) dst[q]     = ((const uint4*)h)[q];
#pragma unroll
    for (int q = 0; q < 4; q++) dst[4 + q] = ((const uint4*)l)[q];
}

__global__ void prep_bias(const float* __restrict__ bk, const float* __restrict__ bq,
                          float* __restrict__ bkq)
{
    int t = threadIdx.x;
    bkq[t] = (t < 64) ? bk[t] : bq[t - 64];
}

// ============================ tcgen05 TMA GEMM ===============================
// BM=256 (two M=128 accumulators), KC=32 packed hi|lo, 3-stage TMA pipeline.
// Deferred-empty-wait mainloop: tensor queue never drains.
// mtoff = m-tile offset (quarter scheduling).
// MODE 0: out = (acc + bias[n]) * aux[m]
// MODE 1: out = aux[m][n] + bias[n] + acc
// MODE 2: out = acc + bias[n]
#define BMg 256
#define KCg 32
#define NCHUNK (DIMc / KCg)      // 128
#define NSTAGE 3
#define SM_DATA0 1024

template<int MODE, int BNv, int OUTW>
__global__ void __launch_bounds__(256, 1)
tc_gemm(const __grid_constant__ CUtensorMap tmA,
        const __grid_constant__ CUtensorMap tmB,
        const float* __restrict__ bias, const float* __restrict__ aux,
        float* __restrict__ out, int mtoff)
{
#if TC_OK
    constexpr int ST_B = BMg * 128;                     // A: 32 KB, then B
    constexpr int STAGE_SZ = (BMg + BNv) * 128;
    constexpr uint32_t TXB = (uint32_t)STAGE_SZ;
    constexpr uint32_t IDESC = 0x08000490u | ((uint32_t)(BNv / 8) << 17);  // M=128

    extern __shared__ __align__(1024) char smem[];
    const uint32_t sb = smem_u32(smem);
    const int tid = threadIdx.x;
    const int wid = tid >> 5;
    const int lid = tid & 31;
    const int m0 = (blockIdx.y + mtoff) * BMg;
    const int n0 = blockIdx.x * BNv;

    // smem: [0] tmem ptr; full[s] @ 16+8s; empty[s] @ 48+8s; stages @ 1024
    if (wid == 0) tmem_alloc(sb + 0, 512);
    if (tid == 0) {
#pragma unroll
        for (int s = 0; s < NSTAGE; s++) {
            mbar_init(sb + 16 + 8 * s, 1);
            mbar_init(sb + 48 + 8 * s, 1);
        }
        async_fence();
    }
    __syncthreads();
    uint32_t tmem;
    asm volatile("ld.shared.b32 %0, [%1];" : "=r"(tmem) : "r"(sb + 0));

    if (tid == 0) {
        int fph[NSTAGE] = {0, 0, 0};
        int eph[NSTAGE] = {0, 0, 0};
        // prologue: stages 0..2 hold chunks 0..2
#pragma unroll
        for (int s = 0; s < NSTAGE; s++) {
            uint32_t st = sb + SM_DATA0 + s * STAGE_SZ;
            mbar_expect_tx(sb + 16 + 8 * s, TXB);
            tma2d(st,        &tmA, s * 64, m0, sb + 16 + 8 * s);
            tma2d(st + ST_B, &tmB, s * 64, n0, sb + 16 + 8 * s);
        }
        for (int i = 0; i < NCHUNK; i++) {
            const int s = i % NSTAGE;
            mbar_wait(sb + 16 + 8 * s, fph[s]); fph[s] ^= 1;
            uint32_t sa = sb + SM_DATA0 + s * STAGE_SZ;
            uint64_t bD = make_desc(sa + ST_B);
#pragma unroll
            for (int d = 0; d < 2; d++) {
                uint64_t aD = make_desc(sa + d * 16384);
                uint32_t D = tmem + d * BNv;
                mma_f16_ss(D, aD + 0, bD + 0, IDESC, (i > 0) ? 1u : 0u);  // hi*hi
                mma_f16_ss(D, aD + 2, bD + 2, IDESC, 1u);
                mma_f16_ss(D, aD + 0, bD + 4, IDESC, 1u);                 // hi*lo
                mma_f16_ss(D, aD + 2, bD + 6, IDESC, 1u);
                mma_f16_ss(D, aD + 4, bD + 0, IDESC, 1u);                 // lo*hi
                mma_f16_ss(D, aD + 6, bD + 2, IDESC, 1u);
            }
            tc_commit(sb + 48 + 8 * s);
            // Deferred refill: stage (i-1)%3 held chunk i-1; once its MMAs
            // retire (while chunk i executes), load chunk i+2 into it.
            if (i >= 1 && i + 2 < NCHUNK) {
                const int sp = (i - 1) % NSTAGE;          // == (i+2) % NSTAGE
                mbar_wait(sb + 48 + 8 * sp, eph[sp]); eph[sp] ^= 1;
                uint32_t sq = sb + SM_DATA0 + sp * STAGE_SZ;
                mbar_expect_tx(sb + 16 + 8 * sp, TXB);
                tma2d(sq,        &tmA, (i + 2) * 64, m0, sb + 16 + 8 * sp);
                tma2d(sq + ST_B, &tmB, (i + 2) * 64, n0, sb + 16 + 8 * sp);
            }
        }
        // wait for last chunk's commit (in-order pipe => all MMAs done)
        const int ls = (NCHUNK - 1) % NSTAGE;
        mbar_wait(sb + 48 + 8 * ls, eph[ls]);
    }
    __syncthreads();
    tc_fence_after();

    // ---- epilogue: 8 warps. wid<4 -> D0 (rows m0+0..127), wid>=4 -> D1.
    {
        const int dsel = wid >> 2;
        const int row = m0 + dsel * 128 + (wid & 3) * 32 + lid;
        const uint32_t dbase = tmem + dsel * BNv;
        float sc = 0.f;
        if (MODE == 0) sc = __ldg(&aux[row]);
#pragma unroll
        for (int cb = 0; cb < BNv / 32; cb++) {
            uint32_t r[32];
            TC_LD_X32(r, dbase + cb * 32);
            TC_WAIT_LD();
            const int nc = n0 + cb * 32;
            float o[32];
#pragma unroll
            for (int j = 0; j < 32; j++) o[j] = __uint_as_float(r[j]);

            const float4* bp = (const float4*)(bias + nc);
            if (MODE == 0) {
#pragma unroll
                for (int q = 0; q < 8; q++) {
                    float4 bv4 = bp[q];
                    o[4*q+0] = (o[4*q+0] + bv4.x) * sc;
                    o[4*q+1] = (o[4*q+1] + bv4.y) * sc;
                    o[4*q+2] = (o[4*q+2] + bv4.z) * sc;
                    o[4*q+3] = (o[4*q+3] + bv4.w) * sc;
                }
            } else if (MODE == 1) {
                const float4* xp = (const float4*)(aux + (size_t)row * OUTW + nc);
#pragma unroll
                for (int q = 0; q < 8; q++) {
                    float4 bv4 = bp[q];
                    float4 xv4 = xp[q];
                    o[4*q+0] += bv4.x + xv4.x;
                    o[4*q+1] += bv4.y + xv4.y;
                    o[4*q+2] += bv4.z + xv4.z;
                    o[4*q+3] += bv4.w + xv4.w;
                }
            } else {
#pragma unroll
                for (int q = 0; q < 8; q++) {
                    float4 bv4 = bp[q];
                    o[4*q+0] += bv4.x;
                    o[4*q+1] += bv4.y;
                    o[4*q+2] += bv4.z;
                    o[4*q+3] += bv4.w;
                }
            }
            float4* op = (float4*)(out + (size_t)row * OUTW + nc);
#pragma unroll
            for (int q = 0; q < 8; q++)
                op[q] = make_float4(o[4*q+0], o[4*q+1], o[4*q+2], o[4*q+3]);
        }
    }
    __syncthreads();
    if (wid == 0) {
        tmem_relinquish();
        tmem_dealloc(tmem, 512);
    }
#else
    asm volatile("trap;");
#endif
}

// ============================ phase post-process =============================
__global__ void __launch_bounds__(256)
phase_post(const float* __restrict__ z, float* __restrict__ scale_out)
{
    const int t = threadIdx.x;
    const int warp = t >> 5, lane = t & 31;
    const int row = blockIdx.x * 8 + warp;
    const float* zr = z + (size_t)row * 128;
    const float PIf = 3.14159265358979323846f;

    float zk0 = zr[lane],      zq0 = zr[64 + lane];
    float zk1 = zr[32 + lane], zq1 = zr[96 + lane];
    float c = cosf((tanhf(zk0) - tanhf(zq0)) * PIf)
            + cosf((tanhf(zk1) - tanhf(zq1)) * PIf);
#pragma unroll
    for (int off = 16; off > 0; off >>= 1)
        c += __shfl_xor_sync(0xFFFFFFFFu, c, off);
    if (lane == 0) {
        float align = c;
        float gain  = log1pf(expf(align / 64.f + 0.5f));
        scale_out[row] = align * gain / 64.f;
    }
}

// ============================ K3: LayerNorm -> packed hi|lo ==================
__global__ void __launch_bounds__(256)
ln_kernel(const float* __restrict__ in, const float* __restrict__ g,
          const float* __restrict__ b, __nv_bfloat16* __restrict__ np, int row0)
{
    const int row = row0 + blockIdx.x;
    const float* rp = in + (size_t)row * DIMc;
    const int t = threadIdx.x;

    float4 v[4];
    float s = 0.f, s2 = 0.f;
#pragma unroll
    for (int i = 0; i < 4; i++) {
        v[i] = *(const float4*)(rp + 4 * (t + 256 * i));
        s  += v[i].x + v[i].y + v[i].z + v[i].w;
        s2 += v[i].x * v[i].x + v[i].y * v[i].y + v[i].z * v[i].z + v[i].w * v[i].w;
    }
#pragma unroll
    for (int off = 16; off > 0; off >>= 1) {
        s  += __shfl_xor_sync(0xFFFFFFFFu, s, off);
        s2 += __shfl_xor_sync(0xFFFFFFFFu, s2, off);
    }
    __shared__ float rs[8], rs2[8];
    __shared__ float mu_s, rstd_s;
    const int wid = t >> 5, lane = t & 31;
    if (lane == 0) { rs[wid] = s; rs2[wid] = s2; }
    __syncthreads();
    if (t == 0) {
        float ts = 0.f, ts2 = 0.f;
#pragma unroll
        for (int i = 0; i < 8; i++) { ts += rs[i]; ts2 += rs2[i]; }
        float mu  = ts / (float)DIMc;
        float var = ts2 / (float)DIMc - mu * mu;
        mu_s   = mu;
        rstd_s = rsqrtf(fmaxf(var, 0.f) + 1e-5f);
    }
    __syncthreads();
    const float mu = mu_s, rstd = rstd_s;
    __nv_bfloat16* nrow = np + (size_t)row * (2 * DIMc);
#pragma unroll
    for (int i = 0; i < 4; i++) {
        int c = 4 * (t + 256 * i);
        float4 gg = *(const float4*)(g + c);
        float4 bb = *(const float4*)(b + c);
        float4 ov;
        ov.x = (v[i].x - mu) * rstd * gg.x + bb.x;
        ov.y = (v[i].y - mu) * rstd * gg.y + bb.y;
        ov.z = (v[i].z - mu) * rstd * gg.z + bb.z;
        ov.w = (v[i].w - mu) * rstd * gg.w + bb.w;
        ushort4 h, l;
        split1(ov.x, h.x, l.x); split1(ov.y, h.y, l.y);
        split1(ov.z, h.z, l.z); split1(ov.w, h.w, l.w);
        const int chunk = c >> 5, off = c & 31;
        __nv_bfloat16* base = nrow + chunk * 64 + off;
        *(ushort4*)(base)      = h;
        *(ushort4*)(base + 32) = l;
    }
}

// ============================ launch =========================================
typedef CUresult (*PFN_encodeTiled)(CUtensorMap*, CUtensorMapDataType, cuuint32_t,
                                    void*, const cuuint64_t*, const cuuint64_t*,
                                    const cuuint32_t*, const cuuint32_t*,
                                    CUtensorMapInterleave, CUtensorMapSwizzle,
                                    CUtensorMapL2promotion, CUtensorMapFloatOOBfill);

static void enc_map(PFN_encodeTiled f, CUtensorMap* m, void* ptr,
                    unsigned long long rows, unsigned box_rows)
{
    cuuint64_t dims[2]    = { (cuuint64_t)(2 * DIMc), (cuuint64_t)rows };
    cuuint64_t strides[1] = { (cuuint64_t)(2 * DIMc) * 2 };   // bytes per row
    cuuint32_t box[2]     = { 64u, box_rows };
    cuuint32_t es[2]      = { 1u, 1u };
    f(m, CU_TENSOR_MAP_DATA_TYPE_BFLOAT16, 2, ptr, dims, strides, box, es,
      CU_TENSOR_MAP_INTERLEAVE_NONE, CU_TENSOR_MAP_SWIZZLE_128B,
      CU_TENSOR_MAP_L2_PROMOTION_L2_128B, CU_TENSOR_MAP_FLOAT_OOB_FILL_NONE);
}

extern "C" void kernel_launch(void* const* d_in, const int* in_sizes, int n_in,
                              void* d_out, int out_size)
{
    (void)in_sizes; (void)n_in; (void)out_size;
    const float* x   = (const float*)d_in[0];
    const float* Wk  = (const float*)d_in[1];
    const float* bk  = (const float*)d_in[2];
    const float* Wq  = (const float*)d_in[3];
    const float* bq  = (const float*)d_in[4];
    const float* Wv  = (const float*)d_in[5];
    const float* bv  = (const float*)d_in[6];
    const float* lng = (const float*)d_in[7];
    const float* lnb = (const float*)d_in[8];
    const float* Wo  = (const float*)d_in[9];
    const float* bo  = (const float*)d_in[10];
    float* out = (float*)d_out;

    void *p;
    cudaGetSymbolAddress(&p, g_scale); float* psc = (float*)p;
    cudaGetSymbolAddress(&p, g_buf1);  float* pb1 = (float*)p;
    cudaGetSymbolAddress(&p, g_phase); float* pph = (float*)p;
    cudaGetSymbolAddress(&p, g_bkq);   float* pbkq = (float*)p;
    cudaGetSymbolAddress(&p, g_xp);    __nv_bfloat16* xp  = (__nv_bfloat16*)p;
    cudaGetSymbolAddress(&p, g_wvp);   __nv_bfloat16* wvp = (__nv_bfloat16*)p;
    cudaGetSymbolAddress(&p, g_wop);   __nv_bfloat16* wop = (__nv_bfloat16*)p;
    cudaGetSymbolAddress(&p, g_np);    __nv_bfloat16* np  = (__nv_bfloat16*)p;
    cudaGetSymbolAddress(&p, g_wkqp);  __nv_bfloat16* wkqp = (__nv_bfloat16*)p;

    // tensor maps (driver entry point; no -lcuda link needed)
    PFN_encodeTiled encf = nullptr;
    {
        void* fp = nullptr;
        cudaDriverEntryPointQueryResult qr;
        cudaGetDriverEntryPoint("cuTensorMapEncodeTiled", &fp, cudaEnableDefault, &qr);
        encf = (PFN_encodeTiled)fp;
    }
    CUtensorMap tmX, tmWv, tmWo, tmN, tmWkq;
    enc_map(encf, &tmX,   xp,   Bc,   256);
    enc_map(encf, &tmWv,  wvp,  DIMc, 256);
    enc_map(encf, &tmWo,  wop,  DIMc, 256);
    enc_map(encf, &tmN,   np,   Bc,   256);
    enc_map(encf, &tmWkq, wkqp, 128,  128);

    constexpr int SMEM_256 = SM_DATA0 + NSTAGE * ((BMg + 256) * 128);  // 197,632
    constexpr int SMEM_128 = SM_DATA0 + NSTAGE * ((BMg + 128) * 128);  // 148,480
    cudaFuncSetAttribute((tc_gemm<0,256,DIMc>), cudaFuncAttributeMaxDynamicSharedMemorySize, SMEM_256);
    cudaFuncSetAttribute((tc_gemm<1,256,DIMc>), cudaFuncAttributeMaxDynamicSharedMemorySize, SMEM_256);
    cudaFuncSetAttribute((tc_gemm<2,128,128>),  cudaFuncAttributeMaxDynamicSharedMemorySize, SMEM_128);

    // one-time side stream + events (created on the uncaptured correctness call)
    static cudaStream_t s1 = nullptr;
    static cudaEvent_t evTop, evG1[4], evEnd;
    if (!s1) {
        cudaStreamCreateWithFlags(&s1, cudaStreamNonBlocking);
        cudaEventCreateWithFlags(&evTop, cudaEventDisableTiming);
        for (int q = 0; q < 4; q++)
            cudaEventCreateWithFlags(&evG1[q], cudaEventDisableTiming);
        cudaEventCreateWithFlags(&evEnd, cudaEventDisableTiming);
    }

    const unsigned nX = Bc * (DIMc / 32);          // 32-elem chunks
    const unsigned nW = DIMc * (DIMc / 32);
    const unsigned nP = 64 * (DIMc / 32);

    // fork: s1 handles Wo split early, then LN+GEMM2 per quarter
    cudaEventRecord(evTop, 0);
    cudaStreamWaitEvent(s1, evTop, 0);
    split_pack<<<(nW + 255) / 256, 256, 0, s1>>>(Wo, wop, nW);

    // main stream: splits + phase + GEMM1 quarters
    split_pack<<<(nX + 255) / 256, 256>>>(x,  xp,  nX);
    split_pack<<<(nW + 255) / 256, 256>>>(Wv, wvp, nW);
    split_pack<<<(nP + 255) / 256, 256>>>(Wk, wkqp, nP);
    split_pack<<<(nP + 255) / 256, 256>>>(Wq, wkqp + (size_t)64 * 2 * DIMc, nP);
    prep_bias<<<1, 128>>>(bk, bq, pbkq);

    tc_gemm<2,128,128><<<dim3(1, 32), 256, SMEM_128>>>(tmX, tmWkq, pbkq, nullptr, pph, 0);
    phase_post<<<Bc / 8, 256>>>(pph, psc);

    constexpr int NMQ = 8;                 // m-tiles per quarter (8*256 = 2048 rows)
    for (int q = 0; q < 4; q++) {
        tc_gemm<0,256,DIMc><<<dim3(DIMc / 256, NMQ), 256, SMEM_256>>>(
            tmX, tmWv, bv, psc, pb1, q * NMQ);
        cudaEventRecord(evG1[q], 0);
    }

    // s1: per quarter, LN then GEMM2 (waits its GEMM1 quarter)
    for (int q = 0; q < 4; q++) {
        cudaStreamWaitEvent(s1, evG1[q], 0);
        ln_kernel<<<NMQ * BMg, 256, 0, s1>>>(pb1, lng, lnb, np, q * NMQ * BMg);
        tc_gemm<1,256,DIMc><<<dim3(DIMc / 256, NMQ), 256, SMEM_256, s1>>>(
            tmN, tmWo, bo, x, out, q * NMQ);
    }
    cudaEventRecord(evEnd, s1);
    cudaStreamWaitEvent(0, evEnd, 0);
}

// round 14
// speedup vs baseline: 1.1298x; 1.0831x over previous
#include <cuda_runtime.h>
#include <cuda.h>
#include <cuda_bf16.h>
#include <math.h>
#include <stdint.h>

#define Bc   8192
#define DIMc 4096
#define Pc   64

// tcgen05 is only available on the arch-specific ('a') compile pass.
#if defined(__CUDA_ARCH__) && (defined(__CUDA_ARCH_FEAT_SM103_ALL) || defined(__CUDA_ARCH_FEAT_SM100_ALL))
#define TC_OK 1
#else
#define TC_OK 0
#endif

// ============================ PTX helpers ====================================
#if TC_OK
__device__ __forceinline__ uint32_t smem_u32(const void* p) {
    uint32_t a;
    asm("{ .reg .u64 t; cvta.to.shared.u64 t, %1; cvt.u32.u64 %0, t; }" : "=r"(a) : "l"(p));
    return a;
}
__device__ __forceinline__ void mbar_init(uint32_t a, uint32_t cnt) {
    asm volatile("mbarrier.init.shared.b64 [%0], %1;" :: "r"(a), "r"(cnt) : "memory");
}
__device__ __forceinline__ void mbar_wait(uint32_t a, uint32_t parity) {
    asm volatile(
        "{\n\t.reg .pred P;\n\t"
        "WL_%=:\n\t"
        "mbarrier.try_wait.parity.acquire.cta.shared::cta.b64 P, [%0], %1, 0x989680;\n\t"
        "@P bra WD_%=;\n\t"
        "bra WL_%=;\n\t"
        "WD_%=:\n\t}"
        :: "r"(a), "r"(parity) : "memory");
}
__device__ __forceinline__ void mbar_expect_tx(uint32_t a, uint32_t bytes) {
    asm volatile("mbarrier.arrive.expect_tx.shared.b64 _, [%0], %1;"
                 :: "r"(a), "r"(bytes) : "memory");
}
__device__ __forceinline__ void tma2d(uint32_t dst, const CUtensorMap* m,
                                      int x, int y, uint32_t mbar) {
    asm volatile(
        "cp.async.bulk.tensor.2d.shared::cta.global.tile.mbarrier::complete_tx::bytes "
        "[%0], [%1, {%2, %3}], [%4];"
        :: "r"(dst), "l"(m), "r"(x), "r"(y), "r"(mbar) : "memory");
}
__device__ __forceinline__ void tmem_alloc(uint32_t dst_smem, uint32_t ncols) {
    asm volatile("tcgen05.alloc.cta_group::1.sync.aligned.shared::cta.b32 [%0], %1;"
                 :: "r"(dst_smem), "r"(ncols) : "memory");
}
__device__ __forceinline__ void tmem_dealloc(uint32_t tmem, uint32_t ncols) {
    asm volatile("tcgen05.dealloc.cta_group::1.sync.aligned.b32 %0, %1;" :: "r"(tmem), "r"(ncols));
}
__device__ __forceinline__ void tmem_relinquish() {
    asm volatile("tcgen05.relinquish_alloc_permit.cta_group::1.sync.aligned;");
}
__device__ __forceinline__ void tc_commit(uint32_t mbar) {
    asm volatile("tcgen05.commit.cta_group::1.mbarrier::arrive::one.shared::cluster.b64 [%0];"
                 :: "r"(mbar) : "memory");
}
__device__ __forceinline__ void tc_fence_after() {
    asm volatile("tcgen05.fence::after_thread_sync;" ::: "memory");
}
__device__ __forceinline__ void async_fence() {
    asm volatile("fence.proxy.async.shared::cta;" ::: "memory");
}
__device__ __forceinline__ void mma_f16_ss(uint32_t d, uint64_t ad, uint64_t bd,
                                           uint32_t idesc, uint32_t enable) {
    asm volatile(
        "{\n\t.reg .pred p;\n\t"
        "setp.ne.u32 p, %4, 0;\n\t"
        "tcgen05.mma.cta_group::1.kind::f16 [%0], %1, %2, %3, {%5, %5, %5, %5}, p;\n\t}"
        :: "r"(d), "l"(ad), "l"(bd), "r"(idesc), "r"(enable), "r"(0u) : "memory");
}
#define TC_LD_X32(r, addr) \
    asm volatile( \
        "tcgen05.ld.sync.aligned.32x32b.x32.b32 " \
        "{%0, %1, %2, %3, %4, %5, %6, %7, " \
        " %8, %9, %10, %11, %12, %13, %14, %15, " \
        " %16, %17, %18, %19, %20, %21, %22, %23, " \
        " %24, %25, %26, %27, %28, %29, %30, %31}, [%32];" \
        : "=r"((r)[0]),  "=r"((r)[1]),  "=r"((r)[2]),  "=r"((r)[3]), \
          "=r"((r)[4]),  "=r"((r)[5]),  "=r"((r)[6]),  "=r"((r)[7]), \
          "=r"((r)[8]),  "=r"((r)[9]),  "=r"((r)[10]), "=r"((r)[11]), \
          "=r"((r)[12]), "=r"((r)[13]), "=r"((r)[14]), "=r"((r)[15]), \
          "=r"((r)[16]), "=r"((r)[17]), "=r"((r)[18]), "=r"((r)[19]), \
          "=r"((r)[20]), "=r"((r)[21]), "=r"((r)[22]), "=r"((r)[23]), \
          "=r"((r)[24]), "=r"((r)[25]), "=r"((r)[26]), "=r"((r)[27]), \
          "=r"((r)[28]), "=r"((r)[29]), "=r"((r)[30]), "=r"((r)[31]) \
        : "r"(addr))
#define TC_WAIT_LD() asm volatile("tcgen05.wait::ld.sync.aligned;" ::: "memory")

// SW128 descriptor: layout=2, version=1, SBO=64, LBO=1
__device__ __forceinline__ uint64_t make_desc(uint32_t addr) {
    const uint64_t base = (uint64_t(2) << 61) | (uint64_t(1) << 46)
                        | (uint64_t(64) << 32) | (uint64_t(1) << 16);
    return base | ((uint64_t)(addr >> 4) & 0x3FFF);
}
#endif // TC_OK

// ============================ scratch globals ================================
// Packed operand layout: [row][2*DIMc] bf16, each 32-K chunk = 128B row:
//   [hi(k0..31) 64B | lo(k0..31) 64B]
__device__ float g_scale[Bc];
__device__ float g_buf1[(size_t)Bc * DIMc];                 // V = x@Wv^T + bv (fp32)
__device__ float g_phase[(size_t)Bc * 128];                 // [kz | qz] pre-activation
__device__ float g_bkq[128];
__device__ __nv_bfloat16 g_xp [(size_t)Bc   * 2 * DIMc];
__device__ __nv_bfloat16 g_wvp[(size_t)DIMc * 2 * DIMc];
__device__ __nv_bfloat16 g_wop[(size_t)DIMc * 2 * DIMc];
__device__ __nv_bfloat16 g_np [(size_t)Bc   * 2 * DIMc];
__device__ __nv_bfloat16 g_wkqp[(size_t)128 * 2 * DIMc];

// ============================ split fp32 -> packed hi|lo =====================
__device__ __forceinline__ void split1(float v, unsigned short &h, unsigned short &l) {
    __nv_bfloat16 hb = __float2bfloat16(v);
    float r = v - __bfloat162float(hb);
    h = __bfloat16_as_ushort(hb);
    l = __bfloat16_as_ushort(__float2bfloat16(r));
}

// one thread per 32-element chunk (chunks are row-major-contiguous)
__global__ void __launch_bounds__(256)
split_pack(const float* __restrict__ in, __nv_bfloat16* __restrict__ outp,
           unsigned nchunks)
{
    unsigned idx = blockIdx.x * 256 + threadIdx.x;
    if (idx >= nchunks) return;
    const float4* src = (const float4*)(in + (size_t)idx * 32);
    unsigned short h[32], l[32];
#pragma unroll
    for (int q = 0; q < 8; q++) {
        float4 v = src[q];
        split1(v.x, h[4*q+0], l[4*q+0]);
        split1(v.y, h[4*q+1], l[4*q+1]);
        split1(v.z, h[4*q+2], l[4*q+2]);
        split1(v.w, h[4*q+3], l[4*q+3]);
    }
    uint4* dst = (uint4*)(outp + (size_t)idx * 64);
#pragma unroll
    for (int q = 0; q < 4; q++) dst[q]     = ((const uint4*)h)[q];
#pragma unroll
    for (int q = 0; q < 4; q++) dst[4 + q] = ((const uint4*)l)[q];
}

__global__ void prep_bias(const float* __restrict__ bk, const float* __restrict__ bq,
                          float* __restrict__ bkq)
{
    int t = threadIdx.x;
    bkq[t] = (t < 64) ? bk[t] : bq[t - 64];
}

// ============================ tcgen05 TMA GEMM ===============================
// BM=256 (two M=128 accumulators), KC=32 packed hi|lo, 3-stage TMA pipeline.
// Deferred-empty-wait mainloop: tensor queue never drains.
// MODE 1: out = aux[m][n] + bias[n] + acc       MODE 2: out = acc + bias[n]
#define BMg 256
#define KCg 32
#define NCHUNK (DIMc / KCg)      // 128
#define NSTAGE 3
#define SM_DATA0 1024

template<int MODE, int BNv, int OUTW>
__global__ void __launch_bounds__(256, 1)
tc_gemm(const __grid_constant__ CUtensorMap tmA,
        const __grid_constant__ CUtensorMap tmB,
        const float* __restrict__ bias, const float* __restrict__ aux,
        float* __restrict__ out, int mtoff)
{
#if TC_OK
    constexpr int ST_B = BMg * 128;                     // A: 32 KB, then B
    constexpr int STAGE_SZ = (BMg + BNv) * 128;
    constexpr uint32_t TXB = (uint32_t)STAGE_SZ;
    constexpr uint32_t IDESC = 0x08000490u | ((uint32_t)(BNv / 8) << 17);  // M=128

    extern __shared__ __align__(1024) char smem[];
    const uint32_t sb = smem_u32(smem);
    const int tid = threadIdx.x;
    const int wid = tid >> 5;
    const int lid = tid & 31;
    const int m0 = (blockIdx.y + mtoff) * BMg;
    const int n0 = blockIdx.x * BNv;

    // smem: [0] tmem ptr; full[s] @ 16+8s; empty[s] @ 48+8s; stages @ 1024
    if (wid == 0) tmem_alloc(sb + 0, 512);
    if (tid == 0) {
#pragma unroll
        for (int s = 0; s < NSTAGE; s++) {
            mbar_init(sb + 16 + 8 * s, 1);
            mbar_init(sb + 48 + 8 * s, 1);
        }
        async_fence();
    }
    __syncthreads();
    uint32_t tmem;
    asm volatile("ld.shared.b32 %0, [%1];" : "=r"(tmem) : "r"(sb + 0));

    if (tid == 0) {
        int fph[NSTAGE] = {0, 0, 0};
        int eph[NSTAGE] = {0, 0, 0};
        // prologue: stages 0..2 hold chunks 0..2
#pragma unroll
        for (int s = 0; s < NSTAGE; s++) {
            uint32_t st = sb + SM_DATA0 + s * STAGE_SZ;
            mbar_expect_tx(sb + 16 + 8 * s, TXB);
            tma2d(st,        &tmA, s * 64, m0, sb + 16 + 8 * s);
            tma2d(st + ST_B, &tmB, s * 64, n0, sb + 16 + 8 * s);
        }
        for (int i = 0; i < NCHUNK; i++) {
            const int s = i % NSTAGE;
            mbar_wait(sb + 16 + 8 * s, fph[s]); fph[s] ^= 1;
            uint32_t sa = sb + SM_DATA0 + s * STAGE_SZ;
            uint64_t bD = make_desc(sa + ST_B);
#pragma unroll
            for (int d = 0; d < 2; d++) {
                uint64_t aD = make_desc(sa + d * 16384);
                uint32_t D = tmem + d * BNv;
                mma_f16_ss(D, aD + 0, bD + 0, IDESC, (i > 0) ? 1u : 0u);  // hi*hi
                mma_f16_ss(D, aD + 2, bD + 2, IDESC, 1u);
                mma_f16_ss(D, aD + 0, bD + 4, IDESC, 1u);                 // hi*lo
                mma_f16_ss(D, aD + 2, bD + 6, IDESC, 1u);
                mma_f16_ss(D, aD + 4, bD + 0, IDESC, 1u);                 // lo*hi
                mma_f16_ss(D, aD + 6, bD + 2, IDESC, 1u);
            }
            tc_commit(sb + 48 + 8 * s);
            // Deferred refill: stage (i-1)%3 held chunk i-1; once its MMAs
            // retire (while chunk i executes), load chunk i+2 into it.
            if (i >= 1 && i + 2 < NCHUNK) {
                const int sp = (i - 1) % NSTAGE;          // == (i+2) % NSTAGE
                mbar_wait(sb + 48 + 8 * sp, eph[sp]); eph[sp] ^= 1;
                uint32_t sq = sb + SM_DATA0 + sp * STAGE_SZ;
                mbar_expect_tx(sb + 16 + 8 * sp, TXB);
                tma2d(sq,        &tmA, (i + 2) * 64, m0, sb + 16 + 8 * sp);
                tma2d(sq + ST_B, &tmB, (i + 2) * 64, n0, sb + 16 + 8 * sp);
            }
        }
        // wait for last chunk's commit (in-order pipe => all MMAs done)
        const int ls = (NCHUNK - 1) % NSTAGE;
        mbar_wait(sb + 48 + 8 * ls, eph[ls]);
    }
    __syncthreads();
    tc_fence_after();

    // ---- epilogue: 8 warps. wid<4 -> D0 (rows m0+0..127), wid>=4 -> D1.
    {
        const int dsel = wid >> 2;
        const int row = m0 + dsel * 128 + (wid & 3) * 32 + lid;
        const uint32_t dbase = tmem + dsel * BNv;
#pragma unroll
        for (int cb = 0; cb < BNv / 32; cb++) {
            uint32_t r[32];
            TC_LD_X32(r, dbase + cb * 32);
            TC_WAIT_LD();
            const int nc = n0 + cb * 32;
            float o[32];
#pragma unroll
            for (int j = 0; j < 32; j++) o[j] = __uint_as_float(r[j]);

            const float4* bp = (const float4*)(bias + nc);
            if (MODE == 1) {
                const float4* xp = (const float4*)(aux + (size_t)row * OUTW + nc);
#pragma unroll
                for (int q = 0; q < 8; q++) {
                    float4 bv4 = bp[q];
                    float4 xv4 = xp[q];
                    o[4*q+0] += bv4.x + xv4.x;
                    o[4*q+1] += bv4.y + xv4.y;
                    o[4*q+2] += bv4.z + xv4.z;
                    o[4*q+3] += bv4.w + xv4.w;
                }
            } else {
#pragma unroll
                for (int q = 0; q < 8; q++) {
                    float4 bv4 = bp[q];
                    o[4*q+0] += bv4.x;
                    o[4*q+1] += bv4.y;
                    o[4*q+2] += bv4.z;
                    o[4*q+3] += bv4.w;
                }
            }
            float4* op = (float4*)(out + (size_t)row * OUTW + nc);
#pragma unroll
            for (int q = 0; q < 8; q++)
                op[q] = make_float4(o[4*q+0], o[4*q+1], o[4*q+2], o[4*q+3]);
        }
    }
    __syncthreads();
    if (wid == 0) {
        tmem_relinquish();
        tmem_dealloc(tmem, 512);
    }
#else
    asm volatile("trap;");
#endif
}

// ============================ phase post-process =============================
__global__ void __launch_bounds__(256)
phase_post(const float* __restrict__ z, float* __restrict__ scale_out)
{
    const int t = threadIdx.x;
    const int warp = t >> 5, lane = t & 31;
    const int row = blockIdx.x * 8 + warp;
    const float* zr = z + (size_t)row * 128;
    const float PIf = 3.14159265358979323846f;

    float zk0 = zr[lane],      zq0 = zr[64 + lane];
    float zk1 = zr[32 + lane], zq1 = zr[96 + lane];
    float c = cosf((tanhf(zk0) - tanhf(zq0)) * PIf)
            + cosf((tanhf(zk1) - tanhf(zq1)) * PIf);
#pragma unroll
    for (int off = 16; off > 0; off >>= 1)
        c += __shfl_xor_sync(0xFFFFFFFFu, c, off);
    if (lane == 0) {
        float align = c;
        float gain  = log1pf(expf(align / 64.f + 0.5f));
        scale_out[row] = align * gain / 64.f;
    }
}

// ============================ K3: scale + LayerNorm -> packed hi|lo ==========
// o = V[row]*sc[row]; then LN(o)*g+b, split to packed hi|lo.
__global__ void __launch_bounds__(256)
ln_kernel(const float* __restrict__ in, const float* __restrict__ g,
          const float* __restrict__ b, __nv_bfloat16* __restrict__ np,
          const float* __restrict__ scv, int row0)
{
    const int row = row0 + blockIdx.x;
    const float* rp = in + (size_t)row * DIMc;
    const int t = threadIdx.x;
    const float srow = __ldg(&scv[row]);

    float4 v[4];
    float s = 0.f, s2 = 0.f;
#pragma unroll
    for (int i = 0; i < 4; i++) {
        v[i] = *(const float4*)(rp + 4 * (t + 256 * i));
        v[i].x *= srow; v[i].y *= srow; v[i].z *= srow; v[i].w *= srow;
        s  += v[i].x + v[i].y + v[i].z + v[i].w;
        s2 += v[i].x * v[i].x + v[i].y * v[i].y + v[i].z * v[i].z + v[i].w * v[i].w;
    }
#pragma unroll
    for (int off = 16; off > 0; off >>= 1) {
        s  += __shfl_xor_sync(0xFFFFFFFFu, s, off);
        s2 += __shfl_xor_sync(0xFFFFFFFFu, s2, off);
    }
    __shared__ float rs[8], rs2[8];
    __shared__ float mu_s, rstd_s;
    const int wid = t >> 5, lane = t & 31;
    if (lane == 0) { rs[wid] = s; rs2[wid] = s2; }
    __syncthreads();
    if (t == 0) {
        float ts = 0.f, ts2 = 0.f;
#pragma unroll
        for (int i = 0; i < 8; i++) { ts += rs[i]; ts2 += rs2[i]; }
        float mu  = ts / (float)DIMc;
        float var = ts2 / (float)DIMc - mu * mu;
        mu_s   = mu;
        rstd_s = rsqrtf(fmaxf(var, 0.f) + 1e-5f);
    }
    __syncthreads();
    const float mu = mu_s, rstd = rstd_s;
    __nv_bfloat16* nrow = np + (size_t)row * (2 * DIMc);
#pragma unroll
    for (int i = 0; i < 4; i++) {
        int c = 4 * (t + 256 * i);
        float4 gg = *(const float4*)(g + c);
        float4 bb = *(const float4*)(b + c);
        float4 ov;
        ov.x = (v[i].x - mu) * rstd * gg.x + bb.x;
        ov.y = (v[i].y - mu) * rstd * gg.y + bb.y;
        ov.z = (v[i].z - mu) * rstd * gg.z + bb.z;
        ov.w = (v[i].w - mu) * rstd * gg.w + bb.w;
        ushort4 h, l;
        split1(ov.x, h.x, l.x); split1(ov.y, h.y, l.y);
        split1(ov.z, h.z, l.z); split1(ov.w, h.w, l.w);
        const int chunk = c >> 5, off = c & 31;
        __nv_bfloat16* base = nrow + chunk * 64 + off;
        *(ushort4*)(base)      = h;
        *(ushort4*)(base + 32) = l;
    }
}

// ============================ launch =========================================
typedef CUresult (*PFN_encodeTiled)(CUtensorMap*, CUtensorMapDataType, cuuint32_t,
                                    void*, const cuuint64_t*, const cuuint64_t*,
                                    const cuuint32_t*, const cuuint32_t*,
                                    CUtensorMapInterleave, CUtensorMapSwizzle,
                                    CUtensorMapL2promotion, CUtensorMapFloatOOBfill);

static void enc_map(PFN_encodeTiled f, CUtensorMap* m, void* ptr,
                    unsigned long long rows, unsigned box_rows)
{
    cuuint64_t dims[2]    = { (cuuint64_t)(2 * DIMc), (cuuint64_t)rows };
    cuuint64_t strides[1] = { (cuuint64_t)(2 * DIMc) * 2 };   // bytes per row
    cuuint32_t box[2]     = { 64u, box_rows };
    cuuint32_t es[2]      = { 1u, 1u };
    f(m, CU_TENSOR_MAP_DATA_TYPE_BFLOAT16, 2, ptr, dims, strides, box, es,
      CU_TENSOR_MAP_INTERLEAVE_NONE, CU_TENSOR_MAP_SWIZZLE_128B,
      CU_TENSOR_MAP_L2_PROMOTION_L2_128B, CU_TENSOR_MAP_FLOAT_OOB_FILL_NONE);
}

extern "C" void kernel_launch(void* const* d_in, const int* in_sizes, int n_in,
                              void* d_out, int out_size)
{
    (void)in_sizes; (void)n_in; (void)out_size;
    const float* x   = (const float*)d_in[0];
    const float* Wk  = (const float*)d_in[1];
    const float* bk  = (const float*)d_in[2];
    const float* Wq  = (const float*)d_in[3];
    const float* bq  = (const float*)d_in[4];
    const float* Wv  = (const float*)d_in[5];
    const float* bv  = (const float*)d_in[6];
    const float* lng = (const float*)d_in[7];
    const float* lnb = (const float*)d_in[8];
    const float* Wo  = (const float*)d_in[9];
    const float* bo  = (const float*)d_in[10];
    float* out = (float*)d_out;

    void *p;
    cudaGetSymbolAddress(&p, g_scale); float* psc = (float*)p;
    cudaGetSymbolAddress(&p, g_buf1);  float* pb1 = (float*)p;
    cudaGetSymbolAddress(&p, g_phase); float* pph = (float*)p;
    cudaGetSymbolAddress(&p, g_bkq);   float* pbkq = (float*)p;
    cudaGetSymbolAddress(&p, g_xp);    __nv_bfloat16* xp  = (__nv_bfloat16*)p;
    cudaGetSymbolAddress(&p, g_wvp);   __nv_bfloat16* wvp = (__nv_bfloat16*)p;
    cudaGetSymbolAddress(&p, g_wop);   __nv_bfloat16* wop = (__nv_bfloat16*)p;
    cudaGetSymbolAddress(&p, g_np);    __nv_bfloat16* np  = (__nv_bfloat16*)p;
    cudaGetSymbolAddress(&p, g_wkqp);  __nv_bfloat16* wkqp = (__nv_bfloat16*)p;

    // tensor maps (driver entry point; no -lcuda link needed)
    PFN_encodeTiled encf = nullptr;
    {
        void* fp = nullptr;
        cudaDriverEntryPointQueryResult qr;
        cudaGetDriverEntryPoint("cuTensorMapEncodeTiled", &fp, cudaEnableDefault, &qr);
        encf = (PFN_encodeTiled)fp;
    }
    CUtensorMap tmX, tmWv, tmWo, tmN, tmWkq;
    enc_map(encf, &tmX,   xp,   Bc,   256);
    enc_map(encf, &tmWv,  wvp,  DIMc, 256);
    enc_map(encf, &tmWo,  wop,  DIMc, 256);
    enc_map(encf, &tmN,   np,   Bc,   256);
    enc_map(encf, &tmWkq, wkqp, 128,  64);    // phase GEMM: BNv=64 boxes

    constexpr int SMEM_256 = SM_DATA0 + NSTAGE * ((BMg + 256) * 128);  // 197,632
    constexpr int SMEM_64  = SM_DATA0 + NSTAGE * ((BMg + 64) * 128);   // 123,904
    cudaFuncSetAttribute((tc_gemm<1,256,DIMc>), cudaFuncAttributeMaxDynamicSharedMemorySize, SMEM_256);
    cudaFuncSetAttribute((tc_gemm<2,256,DIMc>), cudaFuncAttributeMaxDynamicSharedMemorySize, SMEM_256);
    cudaFuncSetAttribute((tc_gemm<2,64,128>),   cudaFuncAttributeMaxDynamicSharedMemorySize, SMEM_64);

    // one-time side streams + events (created on the uncaptured correctness call)
    static cudaStream_t s1 = nullptr, s2 = nullptr;
    static cudaEvent_t evTop, evX, evWo, evG1[4], evEnd;
    if (!s1) {
        cudaStreamCreateWithFlags(&s1, cudaStreamNonBlocking);
        cudaStreamCreateWithFlags(&s2, cudaStreamNonBlocking);
        cudaEventCreateWithFlags(&evTop, cudaEventDisableTiming);
        cudaEventCreateWithFlags(&evX,   cudaEventDisableTiming);
        cudaEventCreateWithFlags(&evWo,  cudaEventDisableTiming);
        for (int q = 0; q < 4; q++)
            cudaEventCreateWithFlags(&evG1[q], cudaEventDisableTiming);
        cudaEventCreateWithFlags(&evEnd, cudaEventDisableTiming);
    }

    const unsigned nX = Bc * (DIMc / 32);          // 32-elem chunks
    const unsigned nW = DIMc * (DIMc / 32);
    const unsigned nP = 64 * (DIMc / 32);

    cudaEventRecord(evTop, 0);
    cudaStreamWaitEvent(s1, evTop, 0);
    cudaStreamWaitEvent(s2, evTop, 0);

    // s2: Wo split, fully off the critical path
    split_pack<<<(nW + 255) / 256, 256, 0, s2>>>(Wo, wop, nW);
    cudaEventRecord(evWo, s2);

    // main (s0): x split -> Wv split -> GEMM1 quarters (no psc dependency!)
    split_pack<<<(nX + 255) / 256, 256>>>(x,  xp,  nX);
    cudaEventRecord(evX, 0);
    split_pack<<<(nW + 255) / 256, 256>>>(Wv, wvp, nW);

    constexpr int NMQ = 8;                 // m-tiles per quarter (8*256 = 2048 rows)
    for (int q = 0; q < 4; q++) {
        tc_gemm<2,256,DIMc><<<dim3(DIMc / 256, NMQ), 256, SMEM_256>>>(
            tmX, tmWv, bv, nullptr, pb1, q * NMQ);
        cudaEventRecord(evG1[q], 0);
    }

    // s1: phase path (concurrent with Wv split + GEMM1), then LN+GEMM2 quarters
    cudaStreamWaitEvent(s1, evX, 0);
    split_pack<<<(nP + 255) / 256, 256, 0, s1>>>(Wk, wkqp, nP);
    split_pack<<<(nP + 255) / 256, 256, 0, s1>>>(Wq, wkqp + (size_t)64 * 2 * DIMc, nP);
    prep_bias<<<1, 128, 0, s1>>>(bk, bq, pbkq);
    tc_gemm<2,64,128><<<dim3(2, 32), 256, SMEM_64, s1>>>(tmX, tmWkq, pbkq, nullptr, pph, 0);
    phase_post<<<Bc / 8, 256, 0, s1>>>(pph, psc);

    cudaStreamWaitEvent(s1, evWo, 0);
    for (int q = 0; q < 4; q++) {
        cudaStreamWaitEvent(s1, evG1[q], 0);
        ln_kernel<<<NMQ * BMg, 256, 0, s1>>>(pb1, lng, lnb, np, psc, q * NMQ * BMg);
        tc_gemm<1,256,DIMc><<<dim3(DIMc / 256, NMQ), 256, SMEM_256, s1>>>(
            tmN, tmWo, bo, x, out, q * NMQ);
    }
    cudaEventRecord(evEnd, s1);
    cudaStreamWaitEvent(0, evEnd, 0);
}

// round 15
// speedup vs baseline: 1.1753x; 1.0403x over previous
#include <cuda_runtime.h>
#include <cuda.h>
#include <cuda_bf16.h>
#include <math.h>
#include <stdint.h>

#define Bc   8192
#define DIMc 4096
#define Pc   64

// tcgen05 is only available on the arch-specific ('a') compile pass.
#if defined(__CUDA_ARCH__) && (defined(__CUDA_ARCH_FEAT_SM103_ALL) || defined(__CUDA_ARCH_FEAT_SM100_ALL))
#define TC_OK 1
#else
#define TC_OK 0
#endif

// ============================ PTX helpers ====================================
#if TC_OK
__device__ __forceinline__ uint32_t smem_u32(const void* p) {
    uint32_t a;
    asm("{ .reg .u64 t; cvta.to.shared.u64 t, %1; cvt.u32.u64 %0, t; }" : "=r"(a) : "l"(p));
    return a;
}
__device__ __forceinline__ void mbar_init(uint32_t a, uint32_t cnt) {
    asm volatile("mbarrier.init.shared.b64 [%0], %1;" :: "r"(a), "r"(cnt) : "memory");
}
__device__ __forceinline__ void mbar_wait(uint32_t a, uint32_t parity) {
    asm volatile(
        "{\n\t.reg .pred P;\n\t"
        "WL_%=:\n\t"
        "mbarrier.try_wait.parity.acquire.cta.shared::cta.b64 P, [%0], %1, 0x989680;\n\t"
        "@P bra WD_%=;\n\t"
        "bra WL_%=;\n\t"
        "WD_%=:\n\t}"
        :: "r"(a), "r"(parity) : "memory");
}
__device__ __forceinline__ void mbar_expect_tx(uint32_t a, uint32_t bytes) {
    asm volatile("mbarrier.arrive.expect_tx.shared.b64 _, [%0], %1;"
                 :: "r"(a), "r"(bytes) : "memory");
}
__device__ __forceinline__ void tma2d(uint32_t dst, const CUtensorMap* m,
                                      int x, int y, uint32_t mbar) {
    asm volatile(
        "cp.async.bulk.tensor.2d.shared::cta.global.tile.mbarrier::complete_tx::bytes "
        "[%0], [%1, {%2, %3}], [%4];"
        :: "r"(dst), "l"(m), "r"(x), "r"(y), "r"(mbar) : "memory");
}
__device__ __forceinline__ void tmem_alloc(uint32_t dst_smem, uint32_t ncols) {
    asm volatile("tcgen05.alloc.cta_group::1.sync.aligned.shared::cta.b32 [%0], %1;"
                 :: "r"(dst_smem), "r"(ncols) : "memory");
}
__device__ __forceinline__ void tmem_dealloc(uint32_t tmem, uint32_t ncols) {
    asm volatile("tcgen05.dealloc.cta_group::1.sync.aligned.b32 %0, %1;" :: "r"(tmem), "r"(ncols));
}
__device__ __forceinline__ void tmem_relinquish() {
    asm volatile("tcgen05.relinquish_alloc_permit.cta_group::1.sync.aligned;");
}
__device__ __forceinline__ void tc_commit(uint32_t mbar) {
    asm volatile("tcgen05.commit.cta_group::1.mbarrier::arrive::one.shared::cluster.b64 [%0];"
                 :: "r"(mbar) : "memory");
}
__device__ __forceinline__ void tc_fence_after() {
    asm volatile("tcgen05.fence::after_thread_sync;" ::: "memory");
}
__device__ __forceinline__ void async_fence() {
    asm volatile("fence.proxy.async.shared::cta;" ::: "memory");
}
__device__ __forceinline__ void mma_f16_ss(uint32_t d, uint64_t ad, uint64_t bd,
                                           uint32_t idesc, uint32_t enable) {
    asm volatile(
        "{\n\t.reg .pred p;\n\t"
        "setp.ne.u32 p, %4, 0;\n\t"
        "tcgen05.mma.cta_group::1.kind::f16 [%0], %1, %2, %3, {%5, %5, %5, %5}, p;\n\t}"
        :: "r"(d), "l"(ad), "l"(bd), "r"(idesc), "r"(enable), "r"(0u) : "memory");
}
#define TC_LD_X32(r, addr) \
    asm volatile( \
        "tcgen05.ld.sync.aligned.32x32b.x32.b32 " \
        "{%0, %1, %2, %3, %4, %5, %6, %7, " \
        " %8, %9, %10, %11, %12, %13, %14, %15, " \
        " %16, %17, %18, %19, %20, %21, %22, %23, " \
        " %24, %25, %26, %27, %28, %29, %30, %31}, [%32];" \
        : "=r"((r)[0]),  "=r"((r)[1]),  "=r"((r)[2]),  "=r"((r)[3]), \
          "=r"((r)[4]),  "=r"((r)[5]),  "=r"((r)[6]),  "=r"((r)[7]), \
          "=r"((r)[8]),  "=r"((r)[9]),  "=r"((r)[10]), "=r"((r)[11]), \
          "=r"((r)[12]), "=r"((r)[13]), "=r"((r)[14]), "=r"((r)[15]), \
          "=r"((r)[16]), "=r"((r)[17]), "=r"((r)[18]), "=r"((r)[19]), \
          "=r"((r)[20]), "=r"((r)[21]), "=r"((r)[22]), "=r"((r)[23]), \
          "=r"((r)[24]), "=r"((r)[25]), "=r"((r)[26]), "=r"((r)[27]), \
          "=r"((r)[28]), "=r"((r)[29]), "=r"((r)[30]), "=r"((r)[31]) \
        : "r"(addr))
#define TC_WAIT_LD() asm volatile("tcgen05.wait::ld.sync.aligned;" ::: "memory")

// SW128 descriptor: layout=2, version=1, SBO=64, LBO=1
__device__ __forceinline__ uint64_t make_desc(uint32_t addr) {
    const uint64_t base = (uint64_t(2) << 61) | (uint64_t(1) << 46)
                        | (uint64_t(64) << 32) | (uint64_t(1) << 16);
    return base | ((uint64_t)(addr >> 4) & 0x3FFF);
}
#endif // TC_OK

// ============================ scratch globals ================================
// Packed operand layout: [row][2*DIMc] bf16, each 32-K chunk = 128B row:
//   [hi(k0..31) 64B | lo(k0..31) 64B]
__device__ float g_scale[Bc];
__device__ float g_buf1[(size_t)Bc * DIMc];                 // V = x@Wv^T + bv (fp32)
__device__ float g_phase[(size_t)Bc * 128];                 // [kz | qz] pre-activation
__device__ float g_bkq[128];
__device__ __nv_bfloat16 g_xp [(size_t)Bc   * 2 * DIMc];
__device__ __nv_bfloat16 g_wvp[(size_t)DIMc * 2 * DIMc];
__device__ __nv_bfloat16 g_wop[(size_t)DIMc * 2 * DIMc];
__device__ __nv_bfloat16 g_np [(size_t)Bc   * 2 * DIMc];
__device__ __nv_bfloat16 g_wkqp[(size_t)128 * 2 * DIMc];

// ============================ split fp32 -> packed hi|lo =====================
__device__ __forceinline__ void split1(float v, unsigned short &h, unsigned short &l) {
    __nv_bfloat16 hb = __float2bfloat16(v);
    float r = v - __bfloat162float(hb);
    h = __bfloat16_as_ushort(hb);
    l = __bfloat16_as_ushort(__float2bfloat16(r));
}

// one thread per 32-element chunk (chunks are row-major-contiguous)
__global__ void __launch_bounds__(256)
split_pack(const float* __restrict__ in, __nv_bfloat16* __restrict__ outp,
           unsigned nchunks)
{
    unsigned idx = blockIdx.x * 256 + threadIdx.x;
    if (idx >= nchunks) return;
    const float4* src = (const float4*)(in + (size_t)idx * 32);
    unsigned short h[32], l[32];
#pragma unroll
    for (int q = 0; q < 8; q++) {
        float4 v = src[q];
        split1(v.x, h[4*q+0], l[4*q+0]);
        split1(v.y, h[4*q+1], l[4*q+1]);
        split1(v.z, h[4*q+2], l[4*q+2]);
        split1(v.w, h[4*q+3], l[4*q+3]);
    }
    uint4* dst = (uint4*)(outp + (size_t)idx * 64);
#pragma unroll
    for (int q = 0; q < 4; q++) dst[q]     = ((const uint4*)h)[q];
#pragma unroll
    for (int q = 0; q < 4; q++) dst[4 + q] = ((const uint4*)l)[q];
}

__global__ void prep_bias(const float* __restrict__ bk, const float* __restrict__ bq,
                          float* __restrict__ bkq)
{
    int t = threadIdx.x;
    bkq[t] = (t < 64) ? bk[t] : bq[t - 64];
}

// ============================ tcgen05 TMA GEMM ===============================
// BM=256 (two M=128 accumulators), KC=32 packed hi|lo, 3-stage TMA pipeline.
// Warp-specialized: warp1 thread = TMA producer, warp0 thread = MMA consumer
// with prefetched full-wait (waits hidden under MMA execution).
// MODE 1: out = aux[m][n] + bias[n] + acc       MODE 2: out = acc + bias[n]
#define BMg 256
#define KCg 32
#define NCHUNK (DIMc / KCg)      // 128
#define NSTAGE 3
#define SM_DATA0 1024

template<int MODE, int BNv, int OUTW>
__global__ void __launch_bounds__(256, 1)
tc_gemm(const __grid_constant__ CUtensorMap tmA,
        const __grid_constant__ CUtensorMap tmB,
        const float* __restrict__ bias, const float* __restrict__ aux,
        float* __restrict__ out, int mtoff)
{
#if TC_OK
    constexpr int ST_B = BMg * 128;                     // A: 32 KB, then B
    constexpr int STAGE_SZ = (BMg + BNv) * 128;
    constexpr uint32_t TXB = (uint32_t)STAGE_SZ;
    constexpr uint32_t IDESC = 0x08000490u | ((uint32_t)(BNv / 8) << 17);  // M=128

    extern __shared__ __align__(1024) char smem[];
    const uint32_t sb = smem_u32(smem);
    const int tid = threadIdx.x;
    const int wid = tid >> 5;
    const int lid = tid & 31;
    const int m0 = (blockIdx.y + mtoff) * BMg;
    const int n0 = blockIdx.x * BNv;

    // smem: [0] tmem ptr; full[s] @ 16+8s; empty[s] @ 48+8s; stages @ 1024
    if (wid == 0) tmem_alloc(sb + 0, 512);
    if (tid == 0) {
#pragma unroll
        for (int s = 0; s < NSTAGE; s++) {
            mbar_init(sb + 16 + 8 * s, 1);
            mbar_init(sb + 48 + 8 * s, 1);
        }
        async_fence();
    }
    __syncthreads();
    uint32_t tmem;
    asm volatile("ld.shared.b32 %0, [%1];" : "=r"(tmem) : "r"(sb + 0));

    if (tid == 32) {
        // ================= PRODUCER (warp 1, one thread) =================
        int eph[NSTAGE] = {0, 0, 0};
#pragma unroll
        for (int s = 0; s < NSTAGE; s++) {
            uint32_t st = sb + SM_DATA0 + s * STAGE_SZ;
            mbar_expect_tx(sb + 16 + 8 * s, TXB);
            tma2d(st,        &tmA, s * 64, m0, sb + 16 + 8 * s);
            tma2d(st + ST_B, &tmB, s * 64, n0, sb + 16 + 8 * s);
        }
        for (int j = NSTAGE; j < NCHUNK; j++) {
            const int s = j % NSTAGE;
            mbar_wait(sb + 48 + 8 * s, eph[s]); eph[s] ^= 1;   // chunk j-3 done
            uint32_t st = sb + SM_DATA0 + s * STAGE_SZ;
            mbar_expect_tx(sb + 16 + 8 * s, TXB);
            tma2d(st,        &tmA, j * 64, m0, sb + 16 + 8 * s);
            tma2d(st + ST_B, &tmB, j * 64, n0, sb + 16 + 8 * s);
        }
    } else if (tid == 0) {
        // ================= CONSUMER (warp 0, one thread) =================
        int fph[NSTAGE] = {0, 0, 0};
        mbar_wait(sb + 16 + 0, 0); fph[0] = 1;
        for (int i = 0; i < NCHUNK; i++) {
            const int s = i % NSTAGE;
            uint32_t sa = sb + SM_DATA0 + s * STAGE_SZ;
            uint64_t bD = make_desc(sa + ST_B);
#pragma unroll
            for (int d = 0; d < 2; d++) {
                uint64_t aD = make_desc(sa + d * 16384);
                uint32_t D = tmem + d * BNv;
                mma_f16_ss(D, aD + 0, bD + 0, IDESC, (i > 0) ? 1u : 0u);  // hi*hi
                mma_f16_ss(D, aD + 2, bD + 2, IDESC, 1u);
                mma_f16_ss(D, aD + 0, bD + 4, IDESC, 1u);                 // hi*lo
                mma_f16_ss(D, aD + 2, bD + 6, IDESC, 1u);
                mma_f16_ss(D, aD + 4, bD + 0, IDESC, 1u);                 // lo*hi
                mma_f16_ss(D, aD + 6, bD + 2, IDESC, 1u);
            }
            tc_commit(sb + 48 + 8 * s);
            // prefetch wait for next stage: overlaps with chunk i's MMAs
            if (i + 1 < NCHUNK) {
                const int sn = (i + 1) % NSTAGE;
                mbar_wait(sb + 16 + 8 * sn, fph[sn]); fph[sn] ^= 1;
            }
        }
        // final drain: stage ls receives T commits total; wait the T-th.
        const int ls = (NCHUNK - 1) % NSTAGE;
        const int T = (NCHUNK - 1 - ls) / NSTAGE + 1;
        mbar_wait(sb + 48 + 8 * ls, (unsigned)(T - 1) & 1u);
    }
    __syncthreads();
    tc_fence_after();

    // ---- epilogue: 8 warps. wid<4 -> D0 (rows m0+0..127), wid>=4 -> D1.
    {
        const int dsel = wid >> 2;
        const int row = m0 + dsel * 128 + (wid & 3) * 32 + lid;
        const uint32_t dbase = tmem + dsel * BNv;
#pragma unroll
        for (int cb = 0; cb < BNv / 32; cb++) {
            uint32_t r[32];
            TC_LD_X32(r, dbase + cb * 32);
            TC_WAIT_LD();
            const int nc = n0 + cb * 32;
            float o[32];
#pragma unroll
            for (int j = 0; j < 32; j++) o[j] = __uint_as_float(r[j]);

            const float4* bp = (const float4*)(bias + nc);
            if (MODE == 1) {
                const float4* xp = (const float4*)(aux + (size_t)row * OUTW + nc);
#pragma unroll
                for (int q = 0; q < 8; q++) {
                    float4 bv4 = bp[q];
                    float4 xv4 = xp[q];
                    o[4*q+0] += bv4.x + xv4.x;
                    o[4*q+1] += bv4.y + xv4.y;
                    o[4*q+2] += bv4.z + xv4.z;
                    o[4*q+3] += bv4.w + xv4.w;
                }
            } else {
#pragma unroll
                for (int q = 0; q < 8; q++) {
                    float4 bv4 = bp[q];
                    o[4*q+0] += bv4.x;
                    o[4*q+1] += bv4.y;
                    o[4*q+2] += bv4.z;
                    o[4*q+3] += bv4.w;
                }
            }
            float4* op = (float4*)(out + (size_t)row * OUTW + nc);
#pragma unroll
            for (int q = 0; q < 8; q++)
                op[q] = make_float4(o[4*q+0], o[4*q+1], o[4*q+2], o[4*q+3]);
        }
    }
    __syncthreads();
    if (wid == 0) {
        tmem_relinquish();
        tmem_dealloc(tmem, 512);
    }
#else
    asm volatile("trap;");
#endif
}

// ============================ phase post-process =============================
__global__ void __launch_bounds__(256)
phase_post(const float* __restrict__ z, float* __restrict__ scale_out)
{
    const int t = threadIdx.x;
    const int warp = t >> 5, lane = t & 31;
    const int row = blockIdx.x * 8 + warp;
    const float* zr = z + (size_t)row * 128;
    const float PIf = 3.14159265358979323846f;

    float zk0 = zr[lane],      zq0 = zr[64 + lane];
    float zk1 = zr[32 + lane], zq1 = zr[96 + lane];
    float c = cosf((tanhf(zk0) - tanhf(zq0)) * PIf)
            + cosf((tanhf(zk1) - tanhf(zq1)) * PIf);
#pragma unroll
    for (int off = 16; off > 0; off >>= 1)
        c += __shfl_xor_sync(0xFFFFFFFFu, c, off);
    if (lane == 0) {
        float align = c;
        float gain  = log1pf(expf(align / 64.f + 0.5f));
        scale_out[row] = align * gain / 64.f;
    }
}

// ============================ K3: scale + LayerNorm -> packed hi|lo ==========
// o = V[row]*sc[row]; then LN(o)*g+b, split to packed hi|lo.
__global__ void __launch_bounds__(256)
ln_kernel(const float* __restrict__ in, const float* __restrict__ g,
          const float* __restrict__ b, __nv_bfloat16* __restrict__ np,
          const float* __restrict__ scv, int row0)
{
    const int row = row0 + blockIdx.x;
    const float* rp = in + (size_t)row * DIMc;
    const int t = threadIdx.x;
    const float srow = __ldg(&scv[row]);

    float4 v[4];
    float s = 0.f, s2 = 0.f;
#pragma unroll
    for (int i = 0; i < 4; i++) {
        v[i] = *(const float4*)(rp + 4 * (t + 256 * i));
        v[i].x *= srow; v[i].y *= srow; v[i].z *= srow; v[i].w *= srow;
        s  += v[i].x + v[i].y + v[i].z + v[i].w;
        s2 += v[i].x * v[i].x + v[i].y * v[i].y + v[i].z * v[i].z + v[i].w * v[i].w;
    }
#pragma unroll
    for (int off = 16; off > 0; off >>= 1) {
        s  += __shfl_xor_sync(0xFFFFFFFFu, s, off);
        s2 += __shfl_xor_sync(0xFFFFFFFFu, s2, off);
    }
    __shared__ float rs[8], rs2[8];
    __shared__ float mu_s, rstd_s;
    const int wid = t >> 5, lane = t & 31;
    if (lane == 0) { rs[wid] = s; rs2[wid] = s2; }
    __syncthreads();
    if (t == 0) {
        float ts = 0.f, ts2 = 0.f;
#pragma unroll
        for (int i = 0; i < 8; i++) { ts += rs[i]; ts2 += rs2[i]; }
        float mu  = ts / (float)DIMc;
        float var = ts2 / (float)DIMc - mu * mu;
        mu_s   = mu;
        rstd_s = rsqrtf(fmaxf(var, 0.f) + 1e-5f);
    }
    __syncthreads();
    const float mu = mu_s, rstd = rstd_s;
    __nv_bfloat16* nrow = np + (size_t)row * (2 * DIMc);
#pragma unroll
    for (int i = 0; i < 4; i++) {
        int c = 4 * (t + 256 * i);
        float4 gg = *(const float4*)(g + c);
        float4 bb = *(const float4*)(b + c);
        float4 ov;
        ov.x = (v[i].x - mu) * rstd * gg.x + bb.x;
        ov.y = (v[i].y - mu) * rstd * gg.y + bb.y;
        ov.z = (v[i].z - mu) * rstd * gg.z + bb.z;
        ov.w = (v[i].w - mu) * rstd * gg.w + bb.w;
        ushort4 h, l;
        split1(ov.x, h.x, l.x); split1(ov.y, h.y, l.y);
        split1(ov.z, h.z, l.z); split1(ov.w, h.w, l.w);
        const int chunk = c >> 5, off = c & 31;
        __nv_bfloat16* base = nrow + chunk * 64 + off;
        *(ushort4*)(base)      = h;
        *(ushort4*)(base + 32) = l;
    }
}

// ============================ launch =========================================
typedef CUresult (*PFN_encodeTiled)(CUtensorMap*, CUtensorMapDataType, cuuint32_t,
                                    void*, const cuuint64_t*, const cuuint64_t*,
                                    const cuuint32_t*, const cuuint32_t*,
                                    CUtensorMapInterleave, CUtensorMapSwizzle,
                                    CUtensorMapL2promotion, CUtensorMapFloatOOBfill);

static void enc_map(PFN_encodeTiled f, CUtensorMap* m, void* ptr,
                    unsigned long long rows, unsigned box_rows)
{
    cuuint64_t dims[2]    = { (cuuint64_t)(2 * DIMc), (cuuint64_t)rows };
    cuuint64_t strides[1] = { (cuuint64_t)(2 * DIMc) * 2 };   // bytes per row
    cuuint32_t box[2]     = { 64u, box_rows };
    cuuint32_t es[2]      = { 1u, 1u };
    f(m, CU_TENSOR_MAP_DATA_TYPE_BFLOAT16, 2, ptr, dims, strides, box, es,
      CU_TENSOR_MAP_INTERLEAVE_NONE, CU_TENSOR_MAP_SWIZZLE_128B,
      CU_TENSOR_MAP_L2_PROMOTION_L2_128B, CU_TENSOR_MAP_FLOAT_OOB_FILL_NONE);
}

extern "C" void kernel_launch(void* const* d_in, const int* in_sizes, int n_in,
                              void* d_out, int out_size)
{
    (void)in_sizes; (void)n_in; (void)out_size;
    const float* x   = (const float*)d_in[0];
    const float* Wk  = (const float*)d_in[1];
    const float* bk  = (const float*)d_in[2];
    const float* Wq  = (const float*)d_in[3];
    const float* bq  = (const float*)d_in[4];
    const float* Wv  = (const float*)d_in[5];
    const float* bv  = (const float*)d_in[6];
    const float* lng = (const float*)d_in[7];
    const float* lnb = (const float*)d_in[8];
    const float* Wo  = (const float*)d_in[9];
    const float* bo  = (const float*)d_in[10];
    float* out = (float*)d_out;

    void *p;
    cudaGetSymbolAddress(&p, g_scale); float* psc = (float*)p;
    cudaGetSymbolAddress(&p, g_buf1);  float* pb1 = (float*)p;
    cudaGetSymbolAddress(&p, g_phase); float* pph = (float*)p;
    cudaGetSymbolAddress(&p, g_bkq);   float* pbkq = (float*)p;
    cudaGetSymbolAddress(&p, g_xp);    __nv_bfloat16* xp  = (__nv_bfloat16*)p;
    cudaGetSymbolAddress(&p, g_wvp);   __nv_bfloat16* wvp = (__nv_bfloat16*)p;
    cudaGetSymbolAddress(&p, g_wop);   __nv_bfloat16* wop = (__nv_bfloat16*)p;
    cudaGetSymbolAddress(&p, g_np);    __nv_bfloat16* np  = (__nv_bfloat16*)p;
    cudaGetSymbolAddress(&p, g_wkqp);  __nv_bfloat16* wkqp = (__nv_bfloat16*)p;

    // tensor maps (driver entry point; no -lcuda link needed)
    PFN_encodeTiled encf = nullptr;
    {
        void* fp = nullptr;
        cudaDriverEntryPointQueryResult qr;
        cudaGetDriverEntryPoint("cuTensorMapEncodeTiled", &fp, cudaEnableDefault, &qr);
        encf = (PFN_encodeTiled)fp;
    }
    CUtensorMap tmX, tmWv, tmWo, tmN, tmWkq;
    enc_map(encf, &tmX,   xp,   Bc,   256);
    enc_map(encf, &tmWv,  wvp,  DIMc, 256);
    enc_map(encf, &tmWo,  wop,  DIMc, 256);
    enc_map(encf, &tmN,   np,   Bc,   256);
    enc_map(encf, &tmWkq, wkqp, 128,  64);    // phase GEMM: BNv=64 boxes

    constexpr int SMEM_256 = SM_DATA0 + NSTAGE * ((BMg + 256) * 128);  // 197,632
    constexpr int SMEM_64  = SM_DATA0 + NSTAGE * ((BMg + 64) * 128);   // 123,904
    cudaFuncSetAttribute((tc_gemm<1,256,DIMc>), cudaFuncAttributeMaxDynamicSharedMemorySize, SMEM_256);
    cudaFuncSetAttribute((tc_gemm<2,256,DIMc>), cudaFuncAttributeMaxDynamicSharedMemorySize, SMEM_256);
    cudaFuncSetAttribute((tc_gemm<2,64,128>),   cudaFuncAttributeMaxDynamicSharedMemorySize, SMEM_64);

    // one-time side streams + events (created on the uncaptured correctness call)
    static cudaStream_t s1 = nullptr, s2 = nullptr;
    static cudaEvent_t evTop, evX, evWo, evG1[4], evEnd;
    if (!s1) {
        cudaStreamCreateWithFlags(&s1, cudaStreamNonBlocking);
        cudaStreamCreateWithFlags(&s2, cudaStreamNonBlocking);
        cudaEventCreateWithFlags(&evTop, cudaEventDisableTiming);
        cudaEventCreateWithFlags(&evX,   cudaEventDisableTiming);
        cudaEventCreateWithFlags(&evWo,  cudaEventDisableTiming);
        for (int q = 0; q < 4; q++)
            cudaEventCreateWithFlags(&evG1[q], cudaEventDisableTiming);
        cudaEventCreateWithFlags(&evEnd, cudaEventDisableTiming);
    }

    const unsigned nX = Bc * (DIMc / 32);          // 32-elem chunks
    const unsigned nW = DIMc * (DIMc / 32);
    const unsigned nP = 64 * (DIMc / 32);

    cudaEventRecord(evTop, 0);
    cudaStreamWaitEvent(s1, evTop, 0);
    cudaStreamWaitEvent(s2, evTop, 0);

    // s2: Wo split, fully off the critical path
    split_pack<<<(nW + 255) / 256, 256, 0, s2>>>(Wo, wop, nW);
    cudaEventRecord(evWo, s2);

    // main (s0): x split -> Wv split -> GEMM1 quarters (no psc dependency)
    split_pack<<<(nX + 255) / 256, 256>>>(x,  xp,  nX);
    cudaEventRecord(evX, 0);
    split_pack<<<(nW + 255) / 256, 256>>>(Wv, wvp, nW);

    constexpr int NMQ = 8;                 // m-tiles per quarter (8*256 = 2048 rows)
    for (int q = 0; q < 4; q++) {
        tc_gemm<2,256,DIMc><<<dim3(DIMc / 256, NMQ), 256, SMEM_256>>>(
            tmX, tmWv, bv, nullptr, pb1, q * NMQ);
        cudaEventRecord(evG1[q], 0);
    }

    // s1: phase path (concurrent with Wv split + GEMM1), then LN+GEMM2 quarters
    cudaStreamWaitEvent(s1, evX, 0);
    split_pack<<<(nP + 255) / 256, 256, 0, s1>>>(Wk, wkqp, nP);
    split_pack<<<(nP + 255) / 256, 256, 0, s1>>>(Wq, wkqp + (size_t)64 * 2 * DIMc, nP);
    prep_bias<<<1, 128, 0, s1>>>(bk, bq, pbkq);
    tc_gemm<2,64,128><<<dim3(2, 32), 256, SMEM_64, s1>>>(tmX, tmWkq, pbkq, nullptr, pph, 0);
    phase_post<<<Bc / 8, 256, 0, s1>>>(pph, psc);

    cudaStreamWaitEvent(s1, evWo, 0);
    for (int q = 0; q < 4; q++) {
        cudaStreamWaitEvent(s1, evG1[q], 0);
        ln_kernel<<<NMQ * BMg, 256, 0, s1>>>(pb1, lng, lnb, np, psc, q * NMQ * BMg);
        tc_gemm<1,256,DIMc><<<dim3(DIMc / 256, NMQ), 256, SMEM_256, s1>>>(
            tmN, tmWo, bo, x, out, q * NMQ);
    }
    cudaEventRecord(evEnd, s1);
    cudaStreamWaitEvent(0, evEnd, 0);
}